// round 5
// baseline (speedup 1.0000x reference)
#include <cuda_runtime.h>
#include <math.h>

// Problem constants
#define NROWS 4096
#define DDIM  768
#define DINNER 256
#define MCTX  32768
#define H1DIM 512
#define H2DIM 256

// ---------------- scratch (device globals; no allocation allowed) ----------------
__device__ float g_S[(size_t)NROWS * MCTX];    // 536 MB: attention scores / probs
__device__ float g_Q[(size_t)NROWS * DINNER];
__device__ float g_X2[(size_t)NROWS * DDIM];
__device__ float g_Qm[(size_t)NROWS * DDIM];
__device__ float g_Km[(size_t)NROWS * DDIM];
__device__ float g_A2[(size_t)NROWS * NROWS];  // 67 MB
__device__ float g_T[(size_t)NROWS * DDIM];
__device__ float g_H[(size_t)NROWS * DDIM];
__device__ float g_H1[(size_t)NROWS * H1DIM];
__device__ float g_H2[(size_t)NROWS * H2DIM];

// ---------------- helpers ----------------
__device__ __forceinline__ float gelu_exact(float x) {
    return 0.5f * x * (1.0f + erff(x * 0.70710678118654752f));
}
__device__ __forceinline__ float softplus_stable(float x) {
    return (x > 20.0f) ? x : log1pf(expf(x));
}

// ---------------- tiled SGEMM ----------------
// C[M,N] = epilogue(scale * A[M,K] @ op(B)), op(B)=B (KxN) or B^T (B is NxK)
// M % 128 == 0, N % 128 == 0, K % 16 == 0 required (true for all uses).
#define BM 128
#define BN 128
#define BK 16
#define TM 8
#define TN 8

#define EPI_NONE 0
#define EPI_BLEND 1          // C = sig(alpha)*v + (1-sig(alpha))*res
#define EPI_BIAS_GELU 2      // C = gelu(v + bias[col])
#define EPI_BIAS_GELU_RES 3  // C = res + gelu(v + bias[col])

template<bool TRANSB, int EPI>
__global__ __launch_bounds__(256, 2)
void gemm_kernel(const float* __restrict__ A, const float* __restrict__ B,
                 const float* __restrict__ bias, const float* __restrict__ res,
                 const float* __restrict__ alpha_ptr,
                 float* __restrict__ C,
                 int M, int N, int K, float scale)
{
    __shared__ float As[BK][BM + 4];
    __shared__ float Bs[BK][BN + 4];

    const int tid = threadIdx.x;
    const int row0 = blockIdx.y * BM;
    const int col0 = blockIdx.x * BN;

    const int tx = tid & 15;        // 0..15 -> columns
    const int ty = tid >> 4;        // 0..15 -> rows
    const int mBase = ty * TM;
    const int nBase = tx * TN;

    float acc[TM][TN];
#pragma unroll
    for (int i = 0; i < TM; i++)
#pragma unroll
        for (int j = 0; j < TN; j++) acc[i][j] = 0.0f;

    for (int k0 = 0; k0 < K; k0 += BK) {
        // A tile: 128 x 16
#pragma unroll
        for (int l = 0; l < 8; l++) {
            int i = tid + l * 256;
            int r = i >> 4;
            int c = i & 15;
            As[c][r] = A[(size_t)(row0 + r) * K + (k0 + c)];
        }
        // B tile: 16 x 128
        if (!TRANSB) {
#pragma unroll
            for (int l = 0; l < 8; l++) {
                int i = tid + l * 256;
                int r = i >> 7;      // k within tile
                int c = i & 127;     // n within tile
                Bs[r][c] = B[(size_t)(k0 + r) * N + (col0 + c)];
            }
        } else {
#pragma unroll
            for (int l = 0; l < 8; l++) {
                int i = tid + l * 256;
                int r = i >> 4;      // n within tile
                int c = i & 15;      // k within tile
                Bs[c][r] = B[(size_t)(col0 + r) * K + (k0 + c)];
            }
        }
        __syncthreads();

#pragma unroll
        for (int kk = 0; kk < BK; kk++) {
            float a[TM], b[TN];
#pragma unroll
            for (int i = 0; i < TM; i++) a[i] = As[kk][mBase + i];
#pragma unroll
            for (int j = 0; j < TN; j++) b[j] = Bs[kk][nBase + j];
#pragma unroll
            for (int i = 0; i < TM; i++)
#pragma unroll
                for (int j = 0; j < TN; j++)
                    acc[i][j] = fmaf(a[i], b[j], acc[i][j]);
        }
        __syncthreads();
    }

    float blend = 0.0f;
    if (EPI == EPI_BLEND) blend = 1.0f / (1.0f + expf(-alpha_ptr[0]));

#pragma unroll
    for (int i = 0; i < TM; i++) {
        const int r = row0 + mBase + i;
#pragma unroll
        for (int j = 0; j < TN; j++) {
            const int c = col0 + nBase + j;
            const size_t idx = (size_t)r * N + c;
            float v = acc[i][j] * scale;
            if (EPI == EPI_NONE) {
                C[idx] = v;
            } else if (EPI == EPI_BLEND) {
                C[idx] = blend * v + (1.0f - blend) * res[idx];
            } else if (EPI == EPI_BIAS_GELU) {
                C[idx] = gelu_exact(v + bias[c]);
            } else { // EPI_BIAS_GELU_RES
                C[idx] = res[idx] + gelu_exact(v + bias[c]);
            }
        }
    }
}

// ---------------- row softmax (in place) ----------------
__global__ void softmax_rows_kernel(float* __restrict__ S, int ncols)
{
    const int row = blockIdx.x;
    float* p = S + (size_t)row * ncols;
    const int t = threadIdx.x;
    const int nt = blockDim.x;
    __shared__ float red[256];

    // pass 1: max
    float m = -INFINITY;
    for (int j = t; j < ncols; j += nt) m = fmaxf(m, p[j]);
    red[t] = m; __syncthreads();
    for (int off = nt >> 1; off > 0; off >>= 1) {
        if (t < off) red[t] = fmaxf(red[t], red[t + off]);
        __syncthreads();
    }
    m = red[0]; __syncthreads();

    // pass 2: sum of exp
    float s = 0.0f;
    for (int j = t; j < ncols; j += nt) s += expf(p[j] - m);
    red[t] = s; __syncthreads();
    for (int off = nt >> 1; off > 0; off >>= 1) {
        if (t < off) red[t] += red[t + off];
        __syncthreads();
    }
    const float inv = 1.0f / red[0];

    // pass 3: write normalized
    for (int j = t; j < ncols; j += nt) p[j] = expf(p[j] - m) * inv;
}

// ---------------- final tiny GEMM (K=256, N=4) + distribution head ----------------
__global__ void head_kernel(const float* __restrict__ h2, const float* __restrict__ W3,
                            const float* __restrict__ b3, float* __restrict__ out)
{
    const int row = blockIdx.x;
    const int t = threadIdx.x;   // 64 threads
    const float* hr = h2 + (size_t)row * H2DIM;

    float a0 = 0.f, a1 = 0.f, a2 = 0.f, a3 = 0.f;
    for (int k = t; k < H2DIM; k += 64) {
        const float hv = hr[k];
        a0 = fmaf(hv, W3[k * 4 + 0], a0);
        a1 = fmaf(hv, W3[k * 4 + 1], a1);
        a2 = fmaf(hv, W3[k * 4 + 2], a2);
        a3 = fmaf(hv, W3[k * 4 + 3], a3);
    }
    __shared__ float s0[64], s1[64], s2[64], s3[64];
    s0[t] = a0; s1[t] = a1; s2[t] = a2; s3[t] = a3;
    __syncthreads();
    for (int off = 32; off > 0; off >>= 1) {
        if (t < off) {
            s0[t] += s0[t + off]; s1[t] += s1[t + off];
            s2[t] += s2[t + off]; s3[t] += s3[t + off];
        }
        __syncthreads();
    }
    if (t == 0) {
        const float r0 = s0[0] + b3[0];
        const float r1 = s1[0] + b3[1];
        const float r2 = s2[0] + b3[2];
        const float r3 = s3[0] + b3[3];
        out[0 * NROWS + row] = r0;                                     // mu
        out[1 * NROWS + row] = softplus_stable(r1) + 1e-6f;            // v
        out[2 * NROWS + row] = fminf(softplus_stable(r2), 28.0f) + 1.01f; // a
        out[3 * NROWS + row] = softplus_stable(r3) + 1e-6f;            // b
    }
}

// ---------------- launch ----------------
static float* sym(const void* s) {
    void* p = nullptr;
    cudaGetSymbolAddress(&p, (const void*)s);
    return (float*)p;
}

extern "C" void kernel_launch(void* const* d_in, const int* in_sizes, int n_in,
                              void* d_out, int out_size)
{
    const float* X      = (const float*)d_in[0];
    const float* ctx_k  = (const float*)d_in[1];
    const float* ctx_v  = (const float*)d_in[2];
    const float* Wq_hop = (const float*)d_in[3];
    const float* alpha  = (const float*)d_in[4];
    const float* Wq_mol = (const float*)d_in[5];
    const float* Wk_mol = (const float*)d_in[6];
    const float* Wg     = (const float*)d_in[7];
    const float* bg     = (const float*)d_in[8];
    const float* W1     = (const float*)d_in[9];
    const float* b1     = (const float*)d_in[10];
    const float* W2     = (const float*)d_in[11];
    const float* b2     = (const float*)d_in[12];
    const float* W3     = (const float*)d_in[13];
    const float* b3     = (const float*)d_in[14];
    float* out = (float*)d_out;

    float* S  = sym(g_S);
    float* Q  = sym(g_Q);
    float* X2 = sym(g_X2);
    float* Qm = sym(g_Qm);
    float* Km = sym(g_Km);
    float* A2 = sym(g_A2);
    float* T  = sym(g_T);
    float* H  = sym(g_H);
    float* H1 = sym(g_H1);
    float* H2 = sym(g_H2);

    const dim3 blk(256);
    const float inv_sqrt_dinner = 0.0625f;                 // 1/sqrt(256)
    const float inv_sqrt_d = 0.036084391824351615f;        // 1/sqrt(768)

    // 1. Q = X @ Wq_hop                               (4096x256, K=768)
    gemm_kernel<false, EPI_NONE><<<dim3(DINNER / BN, NROWS / BM), blk>>>(
        X, Wq_hop, nullptr, nullptr, nullptr, Q, NROWS, DINNER, DDIM, 1.0f);

    // 2. S = (Q @ ctx_k^T) / 16                       (4096x32768, K=256)
    gemm_kernel<true, EPI_NONE><<<dim3(MCTX / BN, NROWS / BM), blk>>>(
        Q, ctx_k, nullptr, nullptr, nullptr, S, NROWS, MCTX, DINNER, inv_sqrt_dinner);

    // 3. softmax rows of S
    softmax_rows_kernel<<<NROWS, 256>>>(S, MCTX);

    // 4. X2 = blend*(S @ ctx_v) + (1-blend)*X         (4096x768, K=32768)
    gemm_kernel<false, EPI_BLEND><<<dim3(DDIM / BN, NROWS / BM), blk>>>(
        S, ctx_v, nullptr, X, alpha, X2, NROWS, DDIM, MCTX, 1.0f);

    // 5. Qm = X2 @ Wq_mol ; Km = X2 @ Wk_mol          (4096x768, K=768)
    gemm_kernel<false, EPI_NONE><<<dim3(DDIM / BN, NROWS / BM), blk>>>(
        X2, Wq_mol, nullptr, nullptr, nullptr, Qm, NROWS, DDIM, DDIM, 1.0f);
    gemm_kernel<false, EPI_NONE><<<dim3(DDIM / BN, NROWS / BM), blk>>>(
        X2, Wk_mol, nullptr, nullptr, nullptr, Km, NROWS, DDIM, DDIM, 1.0f);

    // 6. A2 = (Qm @ Km^T) / sqrt(768)                 (4096x4096, K=768)
    gemm_kernel<true, EPI_NONE><<<dim3(NROWS / BN, NROWS / BM), blk>>>(
        Qm, Km, nullptr, nullptr, nullptr, A2, NROWS, NROWS, DDIM, inv_sqrt_d);

    // 7. softmax rows of A2 (Dinv == 1 after softmax; renorm is O(1e-7), skipped)
    softmax_rows_kernel<<<NROWS, 256>>>(A2, NROWS);

    // 8. T = A2 @ X2                                  (4096x768, K=4096)
    gemm_kernel<false, EPI_NONE><<<dim3(DDIM / BN, NROWS / BM), blk>>>(
        A2, X2, nullptr, nullptr, nullptr, T, NROWS, DDIM, NROWS, 1.0f);

    // 9. H = X2 + gelu(T @ Wg + bg)                   (4096x768, K=768)
    gemm_kernel<false, EPI_BIAS_GELU_RES><<<dim3(DDIM / BN, NROWS / BM), blk>>>(
        T, Wg, bg, X2, nullptr, H, NROWS, DDIM, DDIM, 1.0f);

    // 10. H1 = gelu(H @ W1 + b1)                      (4096x512, K=768)
    gemm_kernel<false, EPI_BIAS_GELU><<<dim3(H1DIM / BN, NROWS / BM), blk>>>(
        H, W1, b1, nullptr, nullptr, H1, NROWS, H1DIM, DDIM, 1.0f);

    // 11. H2 = gelu(H1 @ W2 + b2)                     (4096x256, K=512)
    gemm_kernel<false, EPI_BIAS_GELU><<<dim3(H2DIM / BN, NROWS / BM), blk>>>(
        H1, W2, b2, nullptr, nullptr, H2, NROWS, H2DIM, H1DIM, 1.0f);

    // 12. r = H2 @ W3 + b3 ; distribution head -> out (mu | v | a | b)
    head_kernel<<<NROWS, 64>>>(H2, W3, b3, out);

    (void)in_sizes; (void)n_in; (void)out_size;
}

// round 7
// speedup vs baseline: 3.4403x; 3.4403x over previous
#include <cuda_runtime.h>
#include <math.h>
#include <stdint.h>

// ---------------- problem constants ----------------
#define NROWS 4096
#define DDIM  768
#define DINNER 256
#define MCTX  32768
#define H1DIM 512
#define H2DIM 256

// ---------------- scratch (device globals; no allocation allowed) ----------------
__device__ float g_S[(size_t)NROWS * MCTX];    // exp(logits) hopfield
__device__ float g_Q[(size_t)NROWS * DINNER];
__device__ float g_X2[(size_t)NROWS * DDIM];
__device__ float g_Qm[(size_t)NROWS * DDIM];
__device__ float g_Km[(size_t)NROWS * DDIM];
__device__ float g_A2[(size_t)NROWS * NROWS];  // exp(logits) mol
__device__ float g_T[(size_t)NROWS * DDIM];
__device__ float g_H[(size_t)NROWS * DDIM];
__device__ float g_H1[(size_t)NROWS * H1DIM];
__device__ float g_H2[(size_t)NROWS * H2DIM];
__device__ float g_invS[NROWS];
__device__ float g_invA[NROWS];
__device__ float g_part[(size_t)8 * NROWS * DDIM];  // split-K partials

// ---------------- helpers ----------------
__device__ __forceinline__ uint32_t smem_u32(const void* p) {
    uint32_t a;
    asm("{ .reg .u64 t; cvta.to.shared.u64 t, %1; cvt.u32.u64 %0, t; }" : "=r"(a) : "l"(p));
    return a;
}
#define SWZ(off) ((off) ^ (((off) >> 3) & 0x70))

__device__ __forceinline__ float tfhi(float x) {
    return __uint_as_float(__float_as_uint(x) & 0xFFFFE000u);
}
__device__ __forceinline__ uint32_t f2tf_rna(float x) {
    uint32_t r; asm("cvt.rna.tf32.f32 %0, %1;" : "=r"(r) : "f"(x)); return r;
}
__device__ __forceinline__ float gelu_exact(float x) {
    return 0.5f * x * (1.0f + erff(x * 0.70710678118654752f));
}
__device__ __forceinline__ float softplus_stable(float x) {
    return (x > 20.0f) ? x : log1pf(expf(x));
}

__device__ __forceinline__ void ldsm4(uint32_t* r, uint32_t addr) {
    asm volatile("ldmatrix.sync.aligned.m8n8.x4.shared.b16 {%0,%1,%2,%3}, [%4];"
        : "=r"(r[0]), "=r"(r[1]), "=r"(r[2]), "=r"(r[3]) : "r"(addr));
}
__device__ __forceinline__ void mma8(float* d, const uint32_t* a, const uint32_t* b) {
    asm volatile("mma.sync.aligned.m16n8k8.row.col.f32.tf32.tf32.f32 "
        "{%0,%1,%2,%3}, {%4,%5,%6,%7}, {%8,%9}, {%0,%1,%2,%3};"
        : "+f"(d[0]), "+f"(d[1]), "+f"(d[2]), "+f"(d[3])
        : "r"(a[0]), "r"(a[1]), "r"(a[2]), "r"(a[3]), "r"(b[0]), "r"(b[1]));
}

// ---------------- GEMM: C[4096,N] = epi(A[4096,K] @ op(B)) ----------------
// Tiles 128x128x32; 8 warps (2m x 4n), warp tile 64x32 via m16n8k8 tf32 mma.
// NSPLIT=3 -> hi/lo 3xTF32 (fp32-class accuracy); NSPLIT=1 -> rna tf32 single pass.
// Smem tile layout per operand: 128 rows x 32 fp32, K-major, Swizzle<3,4,3>.
#define EPI_NONE 0
#define EPI_EXP 1          // exp(v*scale)
#define EPI_RS 2           // v*rowscale[r]
#define EPI_BG 3           // gelu(v + bias[c])
#define EPI_BGR 4          // res + gelu(v + bias[c])

template<bool TRANSB, int EPI, int NSPLIT>
__global__ __launch_bounds__(256)
void mma_gemm(const float* __restrict__ A, const float* __restrict__ B,
              const float* __restrict__ bias, const float* __restrict__ res,
              const float* __restrict__ rowscale,
              float* __restrict__ C, int N, int Ktot, int kLen, float scale)
{
    extern __shared__ char smem[];
    const int tid = threadIdx.x;
    const int lane = tid & 31;
    const int wid = tid >> 5;
    const int warp_m = wid >> 2;     // 0..1  (64 rows each)
    const int warp_n = wid & 3;      // 0..3  (32 cols each)
    const int row0 = blockIdx.y * 128;
    const int col0 = blockIdx.x * 128;
    const int kOff = blockIdx.z * kLen;
    if (blockIdx.z) C += (size_t)blockIdx.z * NROWS * N;

    const uint32_t STG = (NSPLIT == 3) ? 65536u : 32768u; // per-buffer bytes
    const uint32_t sb = smem_u32(smem);

    float4 ra[4], rb[4];
    float d[4][4][4];
#pragma unroll
    for (int i = 0; i < 4; i++)
#pragma unroll
        for (int j = 0; j < 4; j++)
#pragma unroll
            for (int q = 0; q < 4; q++) d[i][j][q] = 0.0f;

    // ---- global load of one 32-wide K chunk into registers ----
    auto gload = [&](int k0) {
#pragma unroll
        for (int l = 0; l < 4; ++l) {
            int idx = tid + l * 256;
            int r = idx >> 3, c4 = idx & 7;
            ra[l] = *(const float4*)(A + (size_t)(row0 + r) * Ktot + kOff + k0 + c4 * 4);
        }
        if (TRANSB) {
#pragma unroll
            for (int l = 0; l < 4; ++l) {
                int idx = tid + l * 256;
                int r = idx >> 3, c4 = idx & 7;
                rb[l] = *(const float4*)(B + (size_t)(col0 + r) * Ktot + kOff + k0 + c4 * 4);
            }
        } else {
#pragma unroll
            for (int l = 0; l < 4; ++l) {
                int k = (lane >> 2) + l * 8;
                int n4 = (lane & 3) + wid * 4;
                rb[l] = *(const float4*)(B + (size_t)(kOff + k0 + k) * N + col0 + n4 * 4);
            }
        }
    };

    // ---- store staged registers into smem buffer ----
    auto sstore = [&](int buf) {
        char* base = smem + buf * STG;
#pragma unroll
        for (int l = 0; l < 4; ++l) {          // A tile
            int idx = tid + l * 256;
            int r = idx >> 3, c4 = idx & 7;
            uint32_t off = SWZ((uint32_t)(r * 128 + c4 * 16));
            if (NSPLIT == 3) {
                float4 h, lo;
                h.x = tfhi(ra[l].x); h.y = tfhi(ra[l].y); h.z = tfhi(ra[l].z); h.w = tfhi(ra[l].w);
                lo.x = ra[l].x - h.x; lo.y = ra[l].y - h.y; lo.z = ra[l].z - h.z; lo.w = ra[l].w - h.w;
                *(float4*)(base + off) = h;
                *(float4*)(base + 32768 + off) = lo;
            } else {
                uint4 t;
                t.x = f2tf_rna(ra[l].x); t.y = f2tf_rna(ra[l].y);
                t.z = f2tf_rna(ra[l].z); t.w = f2tf_rna(ra[l].w);
                *(uint4*)(base + off) = t;
            }
        }
        if (TRANSB) {
#pragma unroll
            for (int l = 0; l < 4; ++l) {      // B tile, n-major rows already
                int idx = tid + l * 256;
                int r = idx >> 3, c4 = idx & 7;
                uint32_t off = SWZ((uint32_t)(r * 128 + c4 * 16));
                if (NSPLIT == 3) {
                    float4 h, lo;
                    h.x = tfhi(rb[l].x); h.y = tfhi(rb[l].y); h.z = tfhi(rb[l].z); h.w = tfhi(rb[l].w);
                    lo.x = rb[l].x - h.x; lo.y = rb[l].y - h.y; lo.z = rb[l].z - h.z; lo.w = rb[l].w - h.w;
                    *(float4*)(base + 16384 + off) = h;
                    *(float4*)(base + 49152 + off) = lo;
                } else {
                    uint4 t;
                    t.x = f2tf_rna(rb[l].x); t.y = f2tf_rna(rb[l].y);
                    t.z = f2tf_rna(rb[l].z); t.w = f2tf_rna(rb[l].w);
                    *(uint4*)(base + 16384 + off) = t;
                }
            }
        } else {
#pragma unroll
            for (int l = 0; l < 4; ++l) {      // B KxN: transpose to n-major
                int k = (lane >> 2) + l * 8;
                int n0 = ((lane & 3) + wid * 4) * 4;
                float v[4] = {rb[l].x, rb[l].y, rb[l].z, rb[l].w};
#pragma unroll
                for (int j = 0; j < 4; ++j) {
                    uint32_t off = SWZ((uint32_t)((n0 + j) * 128 + k * 4));
                    if (NSPLIT == 3) {
                        float h = tfhi(v[j]);
                        *(float*)(base + 16384 + off) = h;
                        *(float*)(base + 49152 + off) = v[j] - h;
                    } else {
                        *(uint32_t*)(base + 16384 + off) = f2tf_rna(v[j]);
                    }
                }
            }
        }
    };

    // ---- mma over one smem buffer ----
    const int lr = lane & 7;
    const int blk = lane >> 3;
    const int aRowB = warp_m * 64 + lr + ((blk & 1) << 3);
    const int aColB = (blk >> 1) << 2;
    const int bRowB = warp_n * 32 + lr + ((blk >> 1) << 3);
    const int bColB = (blk & 1) << 2;

    auto compute = [&](int buf) {
        uint32_t aB = sb + buf * STG;
        uint32_t bB = aB + 16384;
#pragma unroll
        for (int ks = 0; ks < 4; ++ks) {
            int kk = ks * 8;
            uint32_t af[4][4], bf[2][4];
#pragma unroll
            for (int mi = 0; mi < 4; ++mi)
                ldsm4(af[mi], aB + SWZ((uint32_t)((aRowB + mi * 16) * 128 + (kk + aColB) * 4)));
#pragma unroll
            for (int nj = 0; nj < 2; ++nj)
                ldsm4(bf[nj], bB + SWZ((uint32_t)((bRowB + nj * 16) * 128 + (kk + bColB) * 4)));
#pragma unroll
            for (int mi = 0; mi < 4; ++mi)
#pragma unroll
                for (int nt = 0; nt < 4; ++nt)
                    mma8(d[mi][nt], af[mi], &bf[nt >> 1][(nt & 1) * 2]);
            if (NSPLIT == 3) {
                uint32_t al[4][4], bl[2][4];
#pragma unroll
                for (int mi = 0; mi < 4; ++mi)
                    ldsm4(al[mi], aB + 32768 + SWZ((uint32_t)((aRowB + mi * 16) * 128 + (kk + aColB) * 4)));
#pragma unroll
                for (int nj = 0; nj < 2; ++nj)
                    ldsm4(bl[nj], aB + 49152 + SWZ((uint32_t)((bRowB + nj * 16) * 128 + (kk + bColB) * 4)));
#pragma unroll
                for (int mi = 0; mi < 4; ++mi)
#pragma unroll
                    for (int nt = 0; nt < 4; ++nt) {
                        mma8(d[mi][nt], af[mi], &bl[nt >> 1][(nt & 1) * 2]); // hi*lo
                        mma8(d[mi][nt], al[mi], &bf[nt >> 1][(nt & 1) * 2]); // lo*hi
                    }
            }
        }
    };

    // ---- mainloop: double-buffered with register prefetch ----
    const int niter = kLen / 32;
    gload(0);
    sstore(0);
    __syncthreads();
    for (int it = 0; it < niter; ++it) {
        const bool more = (it + 1 < niter);
        if (more) gload((it + 1) * 32);
        compute(it & 1);
        if (more) sstore((it + 1) & 1);
        __syncthreads();
    }

    // ---- epilogue (direct from accumulators; 32B-sector-aligned float2 stores) ----
    const int g = lane >> 2, t4 = lane & 3;
#pragma unroll
    for (int mi = 0; mi < 4; ++mi) {
#pragma unroll
        for (int hf = 0; hf < 2; ++hf) {
            int row = row0 + warp_m * 64 + mi * 16 + g + hf * 8;
            float rs = 1.0f;
            if (EPI == EPI_RS) rs = rowscale[row];
#pragma unroll
            for (int nt = 0; nt < 4; ++nt) {
                int col = col0 + warp_n * 32 + nt * 8 + t4 * 2;
                size_t gi = (size_t)row * N + col;
                float vx = d[mi][nt][hf * 2 + 0];
                float vy = d[mi][nt][hf * 2 + 1];
                if (EPI == EPI_NONE) {
                    vx *= scale; vy *= scale;
                } else if (EPI == EPI_EXP) {
                    vx = expf(vx * scale); vy = expf(vy * scale);
                } else if (EPI == EPI_RS) {
                    vx *= rs; vy *= rs;
                } else if (EPI == EPI_BG) {
                    float2 bv = *(const float2*)(bias + col);
                    vx = gelu_exact(vx + bv.x); vy = gelu_exact(vy + bv.y);
                } else { // EPI_BGR
                    float2 bv = *(const float2*)(bias + col);
                    float2 rv = *(const float2*)(res + gi);
                    vx = rv.x + gelu_exact(vx + bv.x);
                    vy = rv.y + gelu_exact(vy + bv.y);
                }
                *(float2*)(C + gi) = make_float2(vx, vy);
            }
        }
    }
}

// ---------------- split-K reduction kernels ----------------
__global__ void reduce_blend_kernel(const float* __restrict__ part, const float* __restrict__ X,
                                    const float* __restrict__ invS, const float* __restrict__ alpha,
                                    float* __restrict__ X2, int nsp)
{
    size_t i = (size_t)blockIdx.x * 256 + threadIdx.x;  // float4 index over 4096x768
    const float4* p = (const float4*)part;
    const size_t stride = (size_t)NROWS * DDIM / 4;
    float4 s = p[i];
    for (int z = 1; z < nsp; ++z) {
        float4 t = p[i + (size_t)z * stride];
        s.x += t.x; s.y += t.y; s.z += t.z; s.w += t.w;
    }
    int row = (int)((i * 4) / DDIM);
    float rs = invS[row];
    float blend = 1.0f / (1.0f + expf(-alpha[0]));
    float4 xv = ((const float4*)X)[i];
    float4 o;
    o.x = blend * (s.x * rs) + (1.0f - blend) * xv.x;
    o.y = blend * (s.y * rs) + (1.0f - blend) * xv.y;
    o.z = blend * (s.z * rs) + (1.0f - blend) * xv.z;
    o.w = blend * (s.w * rs) + (1.0f - blend) * xv.w;
    ((float4*)X2)[i] = o;
}

__global__ void reduce_rs_kernel(const float* __restrict__ part, const float* __restrict__ invA,
                                 float* __restrict__ T, int nsp)
{
    size_t i = (size_t)blockIdx.x * 256 + threadIdx.x;
    const float4* p = (const float4*)part;
    const size_t stride = (size_t)NROWS * DDIM / 4;
    float4 s = p[i];
    for (int z = 1; z < nsp; ++z) {
        float4 t = p[i + (size_t)z * stride];
        s.x += t.x; s.y += t.y; s.z += t.z; s.w += t.w;
    }
    int row = (int)((i * 4) / DDIM);
    float rs = invA[row];
    s.x *= rs; s.y *= rs; s.z *= rs; s.w *= rs;
    ((float4*)T)[i] = s;
}

// ---------------- row sum -> inverse ----------------
__global__ void rowsum_inv_kernel(const float* __restrict__ S, float* __restrict__ inv, int ncols)
{
    const int row = blockIdx.x;
    const float* p = S + (size_t)row * ncols;
    const int t = threadIdx.x;
    float s = 0.0f;
    for (int j = t * 4; j < ncols; j += 1024) {
        float4 v = *(const float4*)(p + j);
        s += (v.x + v.y) + (v.z + v.w);
    }
    __shared__ float red[256];
    red[t] = s; __syncthreads();
    for (int off = 128; off > 0; off >>= 1) {
        if (t < off) red[t] += red[t + off];
        __syncthreads();
    }
    if (t == 0) inv[row] = 1.0f / red[0];
}

// ---------------- final head ----------------
__global__ void head_kernel(const float* __restrict__ h2, const float* __restrict__ W3,
                            const float* __restrict__ b3, float* __restrict__ out)
{
    const int row = blockIdx.x;
    const int t = threadIdx.x;   // 64 threads
    const float* hr = h2 + (size_t)row * H2DIM;

    float a0 = 0.f, a1 = 0.f, a2 = 0.f, a3 = 0.f;
    for (int k = t; k < H2DIM; k += 64) {
        const float hv = hr[k];
        a0 = fmaf(hv, W3[k * 4 + 0], a0);
        a1 = fmaf(hv, W3[k * 4 + 1], a1);
        a2 = fmaf(hv, W3[k * 4 + 2], a2);
        a3 = fmaf(hv, W3[k * 4 + 3], a3);
    }
    __shared__ float s0[64], s1[64], s2[64], s3[64];
    s0[t] = a0; s1[t] = a1; s2[t] = a2; s3[t] = a3;
    __syncthreads();
    for (int off = 32; off > 0; off >>= 1) {
        if (t < off) {
            s0[t] += s0[t + off]; s1[t] += s1[t + off];
            s2[t] += s2[t + off]; s3[t] += s3[t + off];
        }
        __syncthreads();
    }
    if (t == 0) {
        const float r0 = s0[0] + b3[0];
        const float r1 = s1[0] + b3[1];
        const float r2 = s2[0] + b3[2];
        const float r3 = s3[0] + b3[3];
        out[0 * NROWS + row] = r0;
        out[1 * NROWS + row] = softplus_stable(r1) + 1e-6f;
        out[2 * NROWS + row] = fminf(softplus_stable(r2), 28.0f) + 1.01f;
        out[3 * NROWS + row] = softplus_stable(r3) + 1e-6f;
    }
}

// ---------------- host side ----------------
static float* sym(const void* s) {
    void* p = nullptr;
    cudaGetSymbolAddress(&p, (const void*)s);
    return (float*)p;
}

template<bool TB, int EPI, int NS>
static void launch_gemm(const float* A, const float* B, const float* bias, const float* res,
                        const float* rowscale, float* C,
                        int N, int Ktot, int splits, float scale)
{
    int smemB = (NS == 3) ? 131072 : 65536;
    cudaFuncSetAttribute(mma_gemm<TB, EPI, NS>, cudaFuncAttributeMaxDynamicSharedMemorySize, smemB);
    dim3 grid(N / 128, NROWS / 128, splits);
    mma_gemm<TB, EPI, NS><<<grid, 256, smemB>>>(A, B, bias, res, rowscale, C, N, Ktot, Ktot / splits, scale);
}

extern "C" void kernel_launch(void* const* d_in, const int* in_sizes, int n_in,
                              void* d_out, int out_size)
{
    const float* X      = (const float*)d_in[0];
    const float* ctx_k  = (const float*)d_in[1];
    const float* ctx_v  = (const float*)d_in[2];
    const float* Wq_hop = (const float*)d_in[3];
    const float* alpha  = (const float*)d_in[4];
    const float* Wq_mol = (const float*)d_in[5];
    const float* Wk_mol = (const float*)d_in[6];
    const float* Wg     = (const float*)d_in[7];
    const float* bg     = (const float*)d_in[8];
    const float* W1     = (const float*)d_in[9];
    const float* b1     = (const float*)d_in[10];
    const float* W2     = (const float*)d_in[11];
    const float* b2     = (const float*)d_in[12];
    const float* W3     = (const float*)d_in[13];
    const float* b3     = (const float*)d_in[14];
    float* out = (float*)d_out;

    float* S    = sym(g_S);
    float* Q    = sym(g_Q);
    float* X2   = sym(g_X2);
    float* Qm   = sym(g_Qm);
    float* Km   = sym(g_Km);
    float* A2   = sym(g_A2);
    float* T    = sym(g_T);
    float* H    = sym(g_H);
    float* H1   = sym(g_H1);
    float* H2   = sym(g_H2);
    float* invS = sym(g_invS);
    float* invA = sym(g_invA);
    float* part = sym(g_part);

    const float inv_sqrt_dinner = 0.0625f;              // 1/sqrt(256)
    const float inv_sqrt_d = 0.036084391824351615f;     // 1/sqrt(768)

    // 1. Q = X @ Wq_hop                            (N=256, K=768)   3xTF32
    launch_gemm<false, EPI_NONE, 3>(X, Wq_hop, nullptr, nullptr, nullptr, Q, DINNER, DDIM, 1, 1.0f);

    // 2. S = exp(Q @ ctx_k^T / 16)                 (N=32768, K=256) tf32 (error damped by blend)
    launch_gemm<true, EPI_EXP, 1>(Q, ctx_k, nullptr, nullptr, nullptr, S, MCTX, DINNER, 1, inv_sqrt_dinner);

    // 3. invS = 1 / rowsum(S)
    rowsum_inv_kernel<<<NROWS, 256>>>(S, invS, MCTX);

    // 4. enriched partials = S @ ctx_v  (K=32768, split-K=8), then
    //    X2 = blend*(invS[r]*sum) + (1-blend)*X
    launch_gemm<false, EPI_NONE, 1>(S, ctx_v, nullptr, nullptr, nullptr, part, DDIM, MCTX, 8, 1.0f);
    reduce_blend_kernel<<<NROWS * DDIM / 1024, 256>>>(part, X, invS, alpha, X2, 8);

    // 5. Qm = X2 @ Wq_mol ; Km = X2 @ Wk_mol       (N=768, K=768)   3xTF32
    launch_gemm<false, EPI_NONE, 3>(X2, Wq_mol, nullptr, nullptr, nullptr, Qm, DDIM, DDIM, 1, 1.0f);
    launch_gemm<false, EPI_NONE, 3>(X2, Wk_mol, nullptr, nullptr, nullptr, Km, DDIM, DDIM, 1, 1.0f);

    // 6. A2 = exp(Qm @ Km^T / sqrt(768))           (N=4096, K=768)  3xTF32
    launch_gemm<true, EPI_EXP, 3>(Qm, Km, nullptr, nullptr, nullptr, A2, NROWS, DDIM, 1, inv_sqrt_d);

    // 7. invA = 1 / rowsum(A2)
    rowsum_inv_kernel<<<NROWS, 256>>>(A2, invA, NROWS);

    // 8. T partials = A2 @ X2  (K=4096, split-K=4); T = invA[r]*sum    3xTF32
    launch_gemm<false, EPI_NONE, 3>(A2, X2, nullptr, nullptr, nullptr, part, DDIM, NROWS, 4, 1.0f);
    reduce_rs_kernel<<<NROWS * DDIM / 1024, 256>>>(part, invA, T, 4);

    // 9. H = X2 + gelu(T @ Wg + bg)                (N=768, K=768)   3xTF32
    launch_gemm<false, EPI_BGR, 3>(T, Wg, bg, X2, nullptr, H, DDIM, DDIM, 1, 1.0f);

    // 10. H1 = gelu(H @ W1 + b1)                   (N=512, K=768)   3xTF32
    launch_gemm<false, EPI_BG, 3>(H, W1, b1, nullptr, nullptr, H1, H1DIM, DDIM, 1, 1.0f);

    // 11. H2 = gelu(H1 @ W2 + b2)                  (N=256, K=512)   3xTF32
    launch_gemm<false, EPI_BG, 3>(H1, W2, b2, nullptr, nullptr, H2, H2DIM, H1DIM, 1, 1.0f);

    // 12. head -> out (mu | v | a | b)
    head_kernel<<<NROWS, 64>>>(H2, W3, b3, out);

    (void)in_sizes; (void)n_in; (void)out_size;
}

// round 8
// speedup vs baseline: 5.3305x; 1.5494x over previous
#include <cuda_runtime.h>
#include <cuda_bf16.h>
#include <math.h>
#include <stdint.h>

// ---------------- problem constants ----------------
#define NROWS 4096
#define DDIM  768
#define DINNER 256
#define MCTX  32768
#define H1DIM 512
#define H2DIM 256

// ---------------- scratch (device globals; no allocation allowed) ----------------
__device__ __nv_bfloat16 g_S[(size_t)NROWS * MCTX];    // exp(logits), bf16 (268 MB)
__device__ __nv_bfloat16 g_Vt[(size_t)DDIM * MCTX];    // ctx_v^T in bf16 (48 MB)
__device__ float g_Q[(size_t)NROWS * DINNER];
__device__ float g_X2[(size_t)NROWS * DDIM];
__device__ float g_Qm[(size_t)NROWS * DDIM];
__device__ float g_Km[(size_t)NROWS * DDIM];
__device__ float g_A2[(size_t)NROWS * NROWS];          // exp(logits), fp32 (67 MB)
__device__ float g_T[(size_t)NROWS * DDIM];
__device__ float g_H[(size_t)NROWS * DDIM];
__device__ float g_H1[(size_t)NROWS * H1DIM];
__device__ float g_H2[(size_t)NROWS * H2DIM];
__device__ float g_invS[NROWS];
__device__ float g_invA[NROWS];
__device__ float g_part[(size_t)8 * NROWS * DDIM];     // split-K partials

// ---------------- helpers ----------------
__device__ __forceinline__ uint32_t smem_u32(const void* p) {
    uint32_t a;
    asm("{ .reg .u64 t; cvta.to.shared.u64 t, %1; cvt.u32.u64 %0, t; }" : "=r"(a) : "l"(p));
    return a;
}
#define SWZ(off) ((off) ^ (((off) >> 3) & 0x70))

// pack two floats -> bf16x2 (x0 in low half)
__device__ __forceinline__ uint32_t packbf(float x0, float x1) {
    uint32_t r;
    asm("cvt.rn.bf16x2.f32 %0, %1, %2;" : "=r"(r) : "f"(x1), "f"(x0));
    return r;
}
__device__ __forceinline__ void splitbf(float x, float& h, float& l) {
    h = __bfloat162float(__float2bfloat16(x));
    l = x - h;
}
__device__ __forceinline__ float gelu_exact(float x) {
    return 0.5f * x * (1.0f + erff(x * 0.70710678118654752f));
}
__device__ __forceinline__ float softplus_stable(float x) {
    return (x > 20.0f) ? x : log1pf(expf(x));
}

__device__ __forceinline__ void ldsm4(uint32_t* r, uint32_t addr) {
    asm volatile("ldmatrix.sync.aligned.m8n8.x4.shared.b16 {%0,%1,%2,%3}, [%4];"
        : "=r"(r[0]), "=r"(r[1]), "=r"(r[2]), "=r"(r[3]) : "r"(addr));
}
__device__ __forceinline__ void mma16(float* d, const uint32_t* a, uint32_t b0, uint32_t b1) {
    asm volatile("mma.sync.aligned.m16n8k16.row.col.f32.bf16.bf16.f32 "
        "{%0,%1,%2,%3}, {%4,%5,%6,%7}, {%8,%9}, {%0,%1,%2,%3};"
        : "+f"(d[0]), "+f"(d[1]), "+f"(d[2]), "+f"(d[3])
        : "r"(a[0]), "r"(a[1]), "r"(a[2]), "r"(a[3]), "r"(b0), "r"(b1));
}

// ---------------- bf16 tensor-core GEMM ----------------
// C[4096,N] = epi(A[4096,K] @ op(B)); 128x128x64 tiles, 8 warps (2m x 4n),
// warp tile 64x32, m16n8k16 bf16 mma, fp32 accum.
// NSPLIT=1: single-pass bf16.  NSPLIT=3: hi/lo split (hh + h*lo + lo*h).
// Smem per operand tile: 128 rows x 64 bf16 = 128 B/row, Swizzle<3,4,3>.
#define EPI_NONE 0
#define EPI_EXP 1          // exp(v*scale)
#define EPI_BG 2           // gelu(v + bias[c])
#define EPI_BGR 3          // res + gelu(v + bias[c])

template<bool TRANSB, int EPI, int NSPLIT, typename AT, typename BT, typename OT>
__global__ __launch_bounds__(256)
void mma_gemm(const AT* __restrict__ A, const BT* __restrict__ B,
              const float* __restrict__ bias, const float* __restrict__ res,
              OT* __restrict__ C, int N, int Ktot, int kLen, float scale)
{
    extern __shared__ char smem[];
    const int tid = threadIdx.x;
    const int lane = tid & 31;
    const int wid = tid >> 5;
    const int warp_m = wid >> 2;     // 0..1  (64 rows each)
    const int warp_n = wid & 3;      // 0..3  (32 cols each)
    const int row0 = blockIdx.y * 128;
    const int col0 = blockIdx.x * 128;
    const int kOff = blockIdx.z * kLen;
    if (blockIdx.z) C += (size_t)blockIdx.z * NROWS * N;

    const uint32_t STG = (NSPLIT == 3) ? 65536u : 32768u;
    const uint32_t sb = smem_u32(smem);

    // register staging for global->smem
    float4 raf[4][2];   // fp32 A rows
    uint4  rab[4];      // bf16 A rows (raw copy)
    float4 rbf[4][2];   // fp32 B rows (TRANSB)
    uint4  rbb[4];      // bf16 B rows (TRANSB)
    float4 rb0[4], rb1[4]; // fp32 B (KxN transpose path)

    float d[4][4][4];
#pragma unroll
    for (int i = 0; i < 4; i++)
#pragma unroll
        for (int j = 0; j < 4; j++)
#pragma unroll
            for (int q = 0; q < 4; q++) d[i][j][q] = 0.0f;

    // ---- global load of one 64-wide K chunk ----
    auto gload = [&](int k0) {
#pragma unroll
        for (int l = 0; l < 4; ++l) {
            int idx = tid + l * 256;
            int r = idx >> 3, c8 = idx & 7;
            if constexpr (sizeof(AT) == 4) {
                const float* ap = (const float*)A + (size_t)(row0 + r) * Ktot + kOff + k0 + c8 * 8;
                raf[l][0] = *(const float4*)ap;
                raf[l][1] = *(const float4*)(ap + 4);
            } else {
                rab[l] = *(const uint4*)((const __nv_bfloat16*)A + (size_t)(row0 + r) * Ktot + kOff + k0 + c8 * 8);
            }
        }
        if (TRANSB) {
#pragma unroll
            for (int l = 0; l < 4; ++l) {
                int idx = tid + l * 256;
                int r = idx >> 3, c8 = idx & 7;
                if constexpr (sizeof(BT) == 4) {
                    const float* bp = (const float*)B + (size_t)(col0 + r) * Ktot + kOff + k0 + c8 * 8;
                    rbf[l][0] = *(const float4*)bp;
                    rbf[l][1] = *(const float4*)(bp + 4);
                } else {
                    rbb[l] = *(const uint4*)((const __nv_bfloat16*)B + (size_t)(col0 + r) * Ktot + kOff + k0 + c8 * 8);
                }
            }
        } else {
            // B is KxN fp32: thread handles k-pair (2kp, 2kp+1) x 4 n
            int kp = lane >> 2;              // 0..7
            int n0 = ((lane & 3) + wid * 4) * 4;
#pragma unroll
            for (int l = 0; l < 4; ++l) {
                int k = (kp + l * 8) * 2;
                const float* bp = (const float*)B + (size_t)(kOff + k0 + k) * N + col0 + n0;
                rb0[l] = *(const float4*)bp;
                rb1[l] = *(const float4*)(bp + N);
            }
        }
    };

    // ---- store staged registers into smem buffer (bf16, swizzled) ----
    auto sstore = [&](int buf) {
        char* base = smem + buf * STG;
#pragma unroll
        for (int l = 0; l < 4; ++l) {          // A tile
            int idx = tid + l * 256;
            int r = idx >> 3, c8 = idx & 7;
            uint32_t off = SWZ((uint32_t)(r * 128 + c8 * 16));
            if constexpr (sizeof(AT) == 4) {
                float4 v0 = raf[l][0], v1 = raf[l][1];
                if (NSPLIT == 1) {
                    uint4 h;
                    h.x = packbf(v0.x, v0.y); h.y = packbf(v0.z, v0.w);
                    h.z = packbf(v1.x, v1.y); h.w = packbf(v1.z, v1.w);
                    *(uint4*)(base + off) = h;
                } else {
                    float h0,l0,h1,l1,h2,l2,h3,l3,h4,l4,h5,l5,h6,l6,h7,l7;
                    splitbf(v0.x,h0,l0); splitbf(v0.y,h1,l1); splitbf(v0.z,h2,l2); splitbf(v0.w,h3,l3);
                    splitbf(v1.x,h4,l4); splitbf(v1.y,h5,l5); splitbf(v1.z,h6,l6); splitbf(v1.w,h7,l7);
                    uint4 hh, ll;
                    hh.x = packbf(h0,h1); hh.y = packbf(h2,h3); hh.z = packbf(h4,h5); hh.w = packbf(h6,h7);
                    ll.x = packbf(l0,l1); ll.y = packbf(l2,l3); ll.z = packbf(l4,l5); ll.w = packbf(l6,l7);
                    *(uint4*)(base + off) = hh;
                    *(uint4*)(base + 32768 + off) = ll;
                }
            } else {
                *(uint4*)(base + off) = rab[l];
            }
        }
        if (TRANSB) {
#pragma unroll
            for (int l = 0; l < 4; ++l) {
                int idx = tid + l * 256;
                int r = idx >> 3, c8 = idx & 7;
                uint32_t off = SWZ((uint32_t)(r * 128 + c8 * 16));
                if constexpr (sizeof(BT) == 4) {
                    float4 v0 = rbf[l][0], v1 = rbf[l][1];
                    if (NSPLIT == 1) {
                        uint4 h;
                        h.x = packbf(v0.x, v0.y); h.y = packbf(v0.z, v0.w);
                        h.z = packbf(v1.x, v1.y); h.w = packbf(v1.z, v1.w);
                        *(uint4*)(base + 16384 + off) = h;
                    } else {
                        float h0,l0,h1,l1,h2,l2,h3,l3,h4,l4,h5,l5,h6,l6,h7,l7;
                        splitbf(v0.x,h0,l0); splitbf(v0.y,h1,l1); splitbf(v0.z,h2,l2); splitbf(v0.w,h3,l3);
                        splitbf(v1.x,h4,l4); splitbf(v1.y,h5,l5); splitbf(v1.z,h6,l6); splitbf(v1.w,h7,l7);
                        uint4 hh, ll;
                        hh.x = packbf(h0,h1); hh.y = packbf(h2,h3); hh.z = packbf(h4,h5); hh.w = packbf(h6,h7);
                        ll.x = packbf(l0,l1); ll.y = packbf(l2,l3); ll.z = packbf(l4,l5); ll.w = packbf(l6,l7);
                        *(uint4*)(base + 16384 + off) = hh;
                        *(uint4*)(base + 49152 + off) = ll;
                    }
                } else {
                    *(uint4*)(base + 16384 + off) = rbb[l];
                }
            }
        } else {
            int kp = lane >> 2;
            int n0 = ((lane & 3) + wid * 4) * 4;
#pragma unroll
            for (int l = 0; l < 4; ++l) {
                int kpl = kp + l * 8;              // k-pair index 0..31
                float v0[4] = {rb0[l].x, rb0[l].y, rb0[l].z, rb0[l].w};
                float v1[4] = {rb1[l].x, rb1[l].y, rb1[l].z, rb1[l].w};
#pragma unroll
                for (int j = 0; j < 4; ++j) {
                    uint32_t off = SWZ((uint32_t)((n0 + j) * 128 + kpl * 4));
                    if (NSPLIT == 1) {
                        *(uint32_t*)(base + 16384 + off) = packbf(v0[j], v1[j]);
                    } else {
                        float ha,la,hb,lb;
                        splitbf(v0[j],ha,la); splitbf(v1[j],hb,lb);
                        *(uint32_t*)(base + 16384 + off) = packbf(ha, hb);
                        *(uint32_t*)(base + 49152 + off) = packbf(la, lb);
                    }
                }
            }
        }
    };

    // ---- ldmatrix addressing ----
    const int lmat = lane >> 3;      // which 8x8 matrix
    const int lrow = lane & 7;
    const int aRowB = warp_m * 64 + ((lmat & 1) << 3) + lrow;
    const int bRowB = warp_n * 32 + ((lmat & 1) << 3) + lrow;
    const int kHalf = (lmat >> 1) << 4;   // 0 or 16 bytes

    auto compute = [&](int buf) {
        uint32_t aB = sb + buf * STG;
        uint32_t bB = aB + 16384;
#pragma unroll
        for (int ks = 0; ks < 4; ++ks) {
            int kb = ks * 32 + kHalf;
            uint32_t af[4][4], bf2[2][4];
#pragma unroll
            for (int mi = 0; mi < 4; ++mi)
                ldsm4(af[mi], aB + SWZ((uint32_t)((aRowB + mi * 16) * 128 + kb)));
#pragma unroll
            for (int nj = 0; nj < 2; ++nj)
                ldsm4(bf2[nj], bB + SWZ((uint32_t)((bRowB + nj * 16) * 128 + kb)));
#pragma unroll
            for (int mi = 0; mi < 4; ++mi)
#pragma unroll
                for (int g = 0; g < 2; ++g)
#pragma unroll
                    for (int s = 0; s < 2; ++s)
                        mma16(d[mi][g * 2 + s], af[mi], bf2[g][s], bf2[g][s + 2]);
            if (NSPLIT == 3) {
                uint32_t al[4][4], bl[2][4];
#pragma unroll
                for (int mi = 0; mi < 4; ++mi)
                    ldsm4(al[mi], aB + 32768 + SWZ((uint32_t)((aRowB + mi * 16) * 128 + kb)));
#pragma unroll
                for (int nj = 0; nj < 2; ++nj)
                    ldsm4(bl[nj], aB + 49152 + SWZ((uint32_t)((bRowB + nj * 16) * 128 + kb)));
#pragma unroll
                for (int mi = 0; mi < 4; ++mi)
#pragma unroll
                    for (int g = 0; g < 2; ++g)
#pragma unroll
                        for (int s = 0; s < 2; ++s) {
                            mma16(d[mi][g * 2 + s], af[mi], bl[g][s], bl[g][s + 2]); // hi*lo
                            mma16(d[mi][g * 2 + s], al[mi], bf2[g][s], bf2[g][s + 2]); // lo*hi
                        }
            }
        }
    };

    // ---- mainloop: double-buffered with register prefetch ----
    const int niter = kLen / 64;
    gload(0);
    sstore(0);
    __syncthreads();
    for (int it = 0; it < niter; ++it) {
        const bool more = (it + 1 < niter);
        if (more) gload((it + 1) * 64);
        compute(it & 1);
        if (more) sstore((it + 1) & 1);
        __syncthreads();
    }

    // ---- epilogue ----
    const int g4 = lane >> 2, t4 = lane & 3;
#pragma unroll
    for (int mi = 0; mi < 4; ++mi) {
#pragma unroll
        for (int hf = 0; hf < 2; ++hf) {
            int row = row0 + warp_m * 64 + mi * 16 + g4 + hf * 8;
#pragma unroll
            for (int nt = 0; nt < 4; ++nt) {
                int col = col0 + warp_n * 32 + nt * 8 + t4 * 2;
                size_t gi = (size_t)row * N + col;
                float vx = d[mi][nt][hf * 2 + 0];
                float vy = d[mi][nt][hf * 2 + 1];
                if (EPI == EPI_NONE) {
                    vx *= scale; vy *= scale;
                } else if (EPI == EPI_EXP) {
                    vx = expf(vx * scale); vy = expf(vy * scale);
                } else if (EPI == EPI_BG) {
                    float2 bv = *(const float2*)(bias + col);
                    vx = gelu_exact(vx + bv.x); vy = gelu_exact(vy + bv.y);
                } else { // EPI_BGR
                    float2 bv = *(const float2*)(bias + col);
                    float2 rv = *(const float2*)(res + gi);
                    vx = rv.x + gelu_exact(vx + bv.x);
                    vy = rv.y + gelu_exact(vy + bv.y);
                }
                if constexpr (sizeof(OT) == 4) {
                    *(float2*)((float*)C + gi) = make_float2(vx, vy);
                } else {
                    *(uint32_t*)((__nv_bfloat16*)C + gi) = packbf(vx, vy);
                }
            }
        }
    }
}

// ---------------- ctx_v transpose+convert: [M][D] fp32 -> [D][M] bf16 ----------------
__global__ void transpose_conv_kernel(const float* __restrict__ src, __nv_bfloat16* __restrict__ dst)
{
    __shared__ float tile[32][33];
    const int m0 = blockIdx.x * 32;
    const int dcol = blockIdx.y * 32;
    const int x = threadIdx.x;
#pragma unroll
    for (int yy = threadIdx.y; yy < 32; yy += 8)
        tile[yy][x] = src[(size_t)(m0 + yy) * DDIM + dcol + x];
    __syncthreads();
#pragma unroll
    for (int yy = threadIdx.y; yy < 32; yy += 8)
        dst[(size_t)(dcol + yy) * MCTX + m0 + x] = __float2bfloat16(tile[x][yy]);
}

// ---------------- split-K reductions ----------------
__global__ void reduce_blend_kernel(const float* __restrict__ part, const float* __restrict__ X,
                                    const float* __restrict__ invS, const float* __restrict__ alpha,
                                    float* __restrict__ X2, int nsp)
{
    size_t i = (size_t)blockIdx.x * 256 + threadIdx.x;
    const float4* p = (const float4*)part;
    const size_t stride = (size_t)NROWS * DDIM / 4;
    float4 s = p[i];
    for (int z = 1; z < nsp; ++z) {
        float4 t = p[i + (size_t)z * stride];
        s.x += t.x; s.y += t.y; s.z += t.z; s.w += t.w;
    }
    int row = (int)((i * 4) / DDIM);
    float rs = invS[row];
    float blend = 1.0f / (1.0f + expf(-alpha[0]));
    float4 xv = ((const float4*)X)[i];
    float4 o;
    o.x = blend * (s.x * rs) + (1.0f - blend) * xv.x;
    o.y = blend * (s.y * rs) + (1.0f - blend) * xv.y;
    o.z = blend * (s.z * rs) + (1.0f - blend) * xv.z;
    o.w = blend * (s.w * rs) + (1.0f - blend) * xv.w;
    ((float4*)X2)[i] = o;
}

__global__ void reduce_rs_kernel(const float* __restrict__ part, const float* __restrict__ invA,
                                 float* __restrict__ T, int nsp)
{
    size_t i = (size_t)blockIdx.x * 256 + threadIdx.x;
    const float4* p = (const float4*)part;
    const size_t stride = (size_t)NROWS * DDIM / 4;
    float4 s = p[i];
    for (int z = 1; z < nsp; ++z) {
        float4 t = p[i + (size_t)z * stride];
        s.x += t.x; s.y += t.y; s.z += t.z; s.w += t.w;
    }
    int row = (int)((i * 4) / DDIM);
    float rs = invA[row];
    s.x *= rs; s.y *= rs; s.z *= rs; s.w *= rs;
    ((float4*)T)[i] = s;
}

// ---------------- row sums ----------------
__global__ void rowsum_inv_bf16_kernel(const __nv_bfloat16* __restrict__ S, float* __restrict__ inv, int ncols)
{
    const int row = blockIdx.x;
    const __nv_bfloat162* p = (const __nv_bfloat162*)(S + (size_t)row * ncols);
    const int t = threadIdx.x;
    float s = 0.0f;
    for (int j = t; j < ncols / 2; j += 256) {
        float2 v = __bfloat1622float2(p[j]);
        s += v.x + v.y;
    }
    __shared__ float red[256];
    red[t] = s; __syncthreads();
    for (int off = 128; off > 0; off >>= 1) {
        if (t < off) red[t] += red[t + off];
        __syncthreads();
    }
    if (t == 0) inv[row] = 1.0f / red[0];
}

__global__ void rowsum_inv_f32_kernel(const float* __restrict__ S, float* __restrict__ inv, int ncols)
{
    const int row = blockIdx.x;
    const float* p = S + (size_t)row * ncols;
    const int t = threadIdx.x;
    float s = 0.0f;
    for (int j = t * 4; j < ncols; j += 1024) {
        float4 v = *(const float4*)(p + j);
        s += (v.x + v.y) + (v.z + v.w);
    }
    __shared__ float red[256];
    red[t] = s; __syncthreads();
    for (int off = 128; off > 0; off >>= 1) {
        if (t < off) red[t] += red[t + off];
        __syncthreads();
    }
    if (t == 0) inv[row] = 1.0f / red[0];
}

// ---------------- final head ----------------
__global__ void head_kernel(const float* __restrict__ h2, const float* __restrict__ W3,
                            const float* __restrict__ b3, float* __restrict__ out)
{
    const int row = blockIdx.x;
    const int t = threadIdx.x;   // 64 threads
    const float* hr = h2 + (size_t)row * H2DIM;

    float a0 = 0.f, a1 = 0.f, a2 = 0.f, a3 = 0.f;
    for (int k = t; k < H2DIM; k += 64) {
        const float hv = hr[k];
        a0 = fmaf(hv, W3[k * 4 + 0], a0);
        a1 = fmaf(hv, W3[k * 4 + 1], a1);
        a2 = fmaf(hv, W3[k * 4 + 2], a2);
        a3 = fmaf(hv, W3[k * 4 + 3], a3);
    }
    __shared__ float s0[64], s1[64], s2[64], s3[64];
    s0[t] = a0; s1[t] = a1; s2[t] = a2; s3[t] = a3;
    __syncthreads();
    for (int off = 32; off > 0; off >>= 1) {
        if (t < off) {
            s0[t] += s0[t + off]; s1[t] += s1[t + off];
            s2[t] += s2[t + off]; s3[t] += s3[t + off];
        }
        __syncthreads();
    }
    if (t == 0) {
        const float r0 = s0[0] + b3[0];
        const float r1 = s1[0] + b3[1];
        const float r2 = s2[0] + b3[2];
        const float r3 = s3[0] + b3[3];
        out[0 * NROWS + row] = r0;
        out[1 * NROWS + row] = softplus_stable(r1) + 1e-6f;
        out[2 * NROWS + row] = fminf(softplus_stable(r2), 28.0f) + 1.01f;
        out[3 * NROWS + row] = softplus_stable(r3) + 1e-6f;
    }
}

// ---------------- host side ----------------
template<typename T>
static T* sym(const void* s) {
    void* p = nullptr;
    cudaGetSymbolAddress(&p, (const void*)s);
    return (T*)p;
}

template<bool TB, int EPI, int NS, typename AT, typename BT, typename OT>
static void launch_gemm(const AT* A, const BT* B, const float* bias, const float* res,
                        OT* C, int N, int Ktot, int splits, float scale)
{
    int smemB = (NS == 3) ? 131072 : 65536;
    cudaFuncSetAttribute(mma_gemm<TB, EPI, NS, AT, BT, OT>,
                         cudaFuncAttributeMaxDynamicSharedMemorySize, smemB);
    dim3 grid(N / 128, NROWS / 128, splits);
    mma_gemm<TB, EPI, NS, AT, BT, OT><<<grid, 256, smemB>>>(A, B, bias, res, C, N, Ktot, Ktot / splits, scale);
}

extern "C" void kernel_launch(void* const* d_in, const int* in_sizes, int n_in,
                              void* d_out, int out_size)
{
    const float* X      = (const float*)d_in[0];
    const float* ctx_k  = (const float*)d_in[1];
    const float* ctx_v  = (const float*)d_in[2];
    const float* Wq_hop = (const float*)d_in[3];
    const float* alpha  = (const float*)d_in[4];
    const float* Wq_mol = (const float*)d_in[5];
    const float* Wk_mol = (const float*)d_in[6];
    const float* Wg     = (const float*)d_in[7];
    const float* bg     = (const float*)d_in[8];
    const float* W1     = (const float*)d_in[9];
    const float* b1     = (const float*)d_in[10];
    const float* W2     = (const float*)d_in[11];
    const float* b2     = (const float*)d_in[12];
    const float* W3     = (const float*)d_in[13];
    const float* b3     = (const float*)d_in[14];
    float* out = (float*)d_out;

    __nv_bfloat16* S  = sym<__nv_bfloat16>(g_S);
    __nv_bfloat16* Vt = sym<__nv_bfloat16>(g_Vt);
    float* Q    = sym<float>(g_Q);
    float* X2   = sym<float>(g_X2);
    float* Qm   = sym<float>(g_Qm);
    float* Km   = sym<float>(g_Km);
    float* A2   = sym<float>(g_A2);
    float* T    = sym<float>(g_T);
    float* H    = sym<float>(g_H);
    float* H1   = sym<float>(g_H1);
    float* H2   = sym<float>(g_H2);
    float* invS = sym<float>(g_invS);
    float* invA = sym<float>(g_invA);
    float* part = sym<float>(g_part);

    const float inv_sqrt_dinner = 0.0625f;              // 1/sqrt(256)
    const float inv_sqrt_d = 0.036084391824351615f;     // 1/sqrt(768)

    // 0. Vt = bf16(ctx_v^T)   (one-time layout fix for the monster GEMM)
    transpose_conv_kernel<<<dim3(MCTX / 32, DDIM / 32), dim3(32, 8)>>>(ctx_v, Vt);

    // 1. Q = X @ Wq_hop                            (N=256, K=768)   2xbf16 split
    launch_gemm<false, EPI_NONE, 3>(X, Wq_hop, (const float*)nullptr, (const float*)nullptr,
                                    Q, DINNER, DDIM, 1, 1.0f);

    // 2. S = exp(Q @ ctx_k^T / 16) -> bf16         (N=32768, K=256) single bf16
    launch_gemm<true, EPI_EXP, 1>(Q, ctx_k, (const float*)nullptr, (const float*)nullptr,
                                  S, MCTX, DINNER, 1, inv_sqrt_dinner);

    // 3. invS = 1 / rowsum(S)
    rowsum_inv_bf16_kernel<<<NROWS, 256>>>(S, invS, MCTX);

    // 4. enriched partials = S @ Vt^T (K=32768, split-K=8, all-bf16 operands);
    //    X2 = blend*(invS[r]*sum) + (1-blend)*X
    launch_gemm<true, EPI_NONE, 1>(S, (const __nv_bfloat16*)Vt, (const float*)nullptr, (const float*)nullptr,
                                   part, DDIM, MCTX, 8, 1.0f);
    reduce_blend_kernel<<<NROWS * DDIM / 1024, 256>>>(part, X, invS, alpha, X2, 8);

    // 5. Qm = X2 @ Wq_mol ; Km = X2 @ Wk_mol       (N=768, K=768)   split
    launch_gemm<false, EPI_NONE, 3>(X2, Wq_mol, (const float*)nullptr, (const float*)nullptr,
                                    Qm, DDIM, DDIM, 1, 1.0f);
    launch_gemm<false, EPI_NONE, 3>(X2, Wk_mol, (const float*)nullptr, (const float*)nullptr,
                                    Km, DDIM, DDIM, 1, 1.0f);

    // 6. A2 = exp(Qm @ Km^T / sqrt(768)) -> fp32   (N=4096, K=768)  split
    launch_gemm<true, EPI_EXP, 3>(Qm, Km, (const float*)nullptr, (const float*)nullptr,
                                  A2, NROWS, DDIM, 1, inv_sqrt_d);

    // 7. invA = 1 / rowsum(A2)
    rowsum_inv_f32_kernel<<<NROWS, 256>>>(A2, invA, NROWS);

    // 8. T partials = A2 @ X2 (K=4096, split-K=4); T = invA[r]*sum   split
    launch_gemm<false, EPI_NONE, 3>(A2, X2, (const float*)nullptr, (const float*)nullptr,
                                    part, DDIM, NROWS, 4, 1.0f);
    reduce_rs_kernel<<<NROWS * DDIM / 1024, 256>>>(part, invA, T, 4);

    // 9. H = X2 + gelu(T @ Wg + bg)                (N=768, K=768)   split
    launch_gemm<false, EPI_BGR, 3>(T, Wg, bg, X2, H, DDIM, DDIM, 1, 1.0f);

    // 10. H1 = gelu(H @ W1 + b1)                   (N=512, K=768)   split
    launch_gemm<false, EPI_BG, 3>(H, W1, b1, (const float*)nullptr, H1, H1DIM, DDIM, 1, 1.0f);

    // 11. H2 = gelu(H1 @ W2 + b2)                  (N=256, K=512)   split
    launch_gemm<false, EPI_BG, 3>(H1, W2, b2, (const float*)nullptr, H2, H2DIM, H1DIM, 1, 1.0f);

    // 12. head -> out (mu | v | a | b)
    head_kernel<<<NROWS, 64>>>(H2, W3, b3, out);

    (void)in_sizes; (void)n_in; (void)out_size;
}

// round 9
// speedup vs baseline: 7.2290x; 1.3562x over previous
#include <cuda_runtime.h>
#include <cuda_bf16.h>
#include <math.h>
#include <stdint.h>

// ---------------- problem constants ----------------
#define NROWS 4096
#define DDIM  768
#define DINNER 256
#define MCTX  32768
#define H1DIM 512
#define H2DIM 256

typedef __nv_bfloat16 bf16;

// ---------------- scratch (device globals; no allocation allowed) ----------------
__device__ bf16 g_S[(size_t)NROWS * MCTX];       // exp(logits) hopfield, bf16
__device__ bf16 g_Vt[(size_t)DDIM * MCTX];       // ctx_v^T bf16
__device__ bf16 g_Kc[(size_t)MCTX * DINNER];     // ctx_k bf16
__device__ bf16 g_Xh[(size_t)NROWS * DDIM];
__device__ bf16 g_Xl[(size_t)NROWS * DDIM];
__device__ bf16 g_Qb[(size_t)NROWS * DINNER];
__device__ bf16 g_X2h[(size_t)NROWS * DDIM];
__device__ bf16 g_X2l[(size_t)NROWS * DDIM];
__device__ bf16 g_X2th[(size_t)DDIM * NROWS];
__device__ bf16 g_X2tl[(size_t)DDIM * NROWS];
__device__ bf16 g_Qmh[(size_t)NROWS * DDIM];
__device__ bf16 g_Qml[(size_t)NROWS * DDIM];
__device__ bf16 g_Kmh[(size_t)NROWS * DDIM];
__device__ bf16 g_Kml[(size_t)NROWS * DDIM];
__device__ bf16 g_A2h[(size_t)NROWS * NROWS];
__device__ bf16 g_A2l[(size_t)NROWS * NROWS];
__device__ bf16 g_Th[(size_t)NROWS * DDIM];
__device__ bf16 g_Tl[(size_t)NROWS * DDIM];
__device__ bf16 g_Hh[(size_t)NROWS * DDIM];
__device__ bf16 g_Hl[(size_t)NROWS * DDIM];
__device__ bf16 g_H1h[(size_t)NROWS * H1DIM];
__device__ bf16 g_H1l[(size_t)NROWS * H1DIM];
// pre-transposed weights (hi/lo)
__device__ bf16 g_Wqh_h[(size_t)DINNER * DDIM];
__device__ bf16 g_Wqh_l[(size_t)DINNER * DDIM];
__device__ bf16 g_Wqm_h[(size_t)DDIM * DDIM];
__device__ bf16 g_Wqm_l[(size_t)DDIM * DDIM];
__device__ bf16 g_Wkm_h[(size_t)DDIM * DDIM];
__device__ bf16 g_Wkm_l[(size_t)DDIM * DDIM];
__device__ bf16 g_Wg_h[(size_t)DDIM * DDIM];
__device__ bf16 g_Wg_l[(size_t)DDIM * DDIM];
__device__ bf16 g_W1_h[(size_t)H1DIM * DDIM];
__device__ bf16 g_W1_l[(size_t)H1DIM * DDIM];
__device__ bf16 g_W2_h[(size_t)H2DIM * H1DIM];
__device__ bf16 g_W2_l[(size_t)H2DIM * H1DIM];
// fp32
__device__ float g_X2[(size_t)NROWS * DDIM];
__device__ float g_H2[(size_t)NROWS * H2DIM];
__device__ float g_invS[NROWS];
__device__ float g_invA[NROWS];
__device__ float g_part[(size_t)8 * NROWS * DDIM];

// ---------------- helpers ----------------
__device__ __forceinline__ uint32_t smem_u32(const void* p) {
    uint32_t a;
    asm("{ .reg .u64 t; cvta.to.shared.u64 t, %1; cvt.u32.u64 %0, t; }" : "=r"(a) : "l"(p));
    return a;
}
#define SWZ(off) ((off) ^ (((off) >> 3) & 0x70))

__device__ __forceinline__ uint32_t packbf(float x0, float x1) {
    uint32_t r;
    asm("cvt.rn.bf16x2.f32 %0, %1, %2;" : "=r"(r) : "f"(x1), "f"(x0));
    return r;
}
__device__ __forceinline__ void splitbf(float x, float& h, float& l) {
    h = __bfloat162float(__float2bfloat16(x));
    l = x - h;
}
__device__ __forceinline__ float gelu_exact(float x) {
    return 0.5f * x * (1.0f + erff(x * 0.70710678118654752f));
}
__device__ __forceinline__ float softplus_stable(float x) {
    return (x > 20.0f) ? x : log1pf(expf(x));
}

__device__ __forceinline__ void cpa16(uint32_t dst, const void* src) {
    asm volatile("cp.async.cg.shared.global [%0], [%1], 16;" :: "r"(dst), "l"(src));
}
__device__ __forceinline__ void cpa_commit() {
    asm volatile("cp.async.commit_group;" ::: "memory");
}
template<int N>
__device__ __forceinline__ void cpa_wait() {
    asm volatile("cp.async.wait_group %0;" :: "n"(N) : "memory");
}

__device__ __forceinline__ void ldsm4(uint32_t* r, uint32_t addr) {
    asm volatile("ldmatrix.sync.aligned.m8n8.x4.shared.b16 {%0,%1,%2,%3}, [%4];"
        : "=r"(r[0]), "=r"(r[1]), "=r"(r[2]), "=r"(r[3]) : "r"(addr));
}
__device__ __forceinline__ void mma16(float* d, const uint32_t* a, uint32_t b0, uint32_t b1) {
    asm volatile("mma.sync.aligned.m16n8k16.row.col.f32.bf16.bf16.f32 "
        "{%0,%1,%2,%3}, {%4,%5,%6,%7}, {%8,%9}, {%0,%1,%2,%3};"
        : "+f"(d[0]), "+f"(d[1]), "+f"(d[2]), "+f"(d[3])
        : "r"(a[0]), "r"(a[1]), "r"(a[2]), "r"(a[3]), "r"(b0), "r"(b1));
}

// ---------------- unified bf16 GEMM (all operands K-major bf16) ----------------
// C[4096,N] = epi(A @ B^T). A rows [4096][K], B rows [N][K].
// PASSES=1: Ah.Bh   PASSES=3: Ah.Bh + Ah.Bl + Al.Bh (hi/lo split = fp32-class)
// 128x128x64 tiles, 8 warps (2m x 4n), m16n8k16 bf16 mma, cp.async 3-stage pipeline.
#define EPI_NONE 0
#define EPI_EXP 1          // exp(v*scale)
#define EPI_BG 2           // gelu(v + bias[c])
#define EPI_BGR 3          // res + gelu(v + bias[c])

#define NST 3

template<int PASSES, int EPI, bool OSPLIT, typename OT>
__global__ __launch_bounds__(256, PASSES == 1 ? 2 : 1)
void bgemm(const bf16* __restrict__ Ah, const bf16* __restrict__ Al,
           const bf16* __restrict__ Bh, const bf16* __restrict__ Bl,
           const float* __restrict__ bias, const float* __restrict__ res,
           OT* __restrict__ C, bf16* __restrict__ Cl,
           int N, int Ktot, int kLen, float scale)
{
    constexpr uint32_t STG = (PASSES == 1) ? 32768u : 65536u; // tiles per stage: Ah,Bh[,Bl,Al]
    extern __shared__ char smem[];
    const uint32_t sb = smem_u32(smem);
    const int tid = threadIdx.x;
    const int lane = tid & 31;
    const int wid = tid >> 5;
    const int warp_m = wid >> 2;
    const int warp_n = wid & 3;
    const int row0 = blockIdx.y * 128;
    const int col0 = blockIdx.x * 128;
    const int kOff = blockIdx.z * kLen;
    if (blockIdx.z) C += (size_t)blockIdx.z * NROWS * N;

    float d[4][4][4];
#pragma unroll
    for (int i = 0; i < 4; i++)
#pragma unroll
        for (int j = 0; j < 4; j++)
#pragma unroll
            for (int q = 0; q < 4; q++) d[i][j][q] = 0.0f;

    const int niter = kLen >> 6;   // K-chunks of 64

    // ---- async issue of one stage (4 cp.async of 16B per tile per thread) ----
    auto issue = [&](int j) {
        const uint32_t sbase = sb + (uint32_t)(j % NST) * STG;
        const int k0 = kOff + j * 64;
#pragma unroll
        for (int l = 0; l < 4; ++l) {
            int c = tid + l * 256;           // 0..1023 chunk id
            int r = c >> 3, c16 = c & 7;     // row, 16B-chunk within 128B row
            uint32_t soff = SWZ((uint32_t)(r * 128 + c16 * 16));
            size_t ga = (size_t)(row0 + r) * Ktot + k0 + c16 * 8;
            size_t gb = (size_t)(col0 + r) * Ktot + k0 + c16 * 8;
            cpa16(sbase + soff, Ah + ga);
            cpa16(sbase + 16384 + soff, Bh + gb);
            if constexpr (PASSES == 3) {
                cpa16(sbase + 32768 + soff, Bl + gb);
                cpa16(sbase + 49152 + soff, Al + ga);
            }
        }
        cpa_commit();
    };

    // ---- ldmatrix addressing (same fragment map as validated R8 kernel) ----
    const int lmat = lane >> 3;
    const int lrow = lane & 7;
    const int aRowB = warp_m * 64 + ((lmat & 1) << 3) + lrow;
    const int bRowB = warp_n * 32 + ((lmat & 1) << 3) + lrow;
    const int kHalf = (lmat >> 1) << 4;

    auto compute = [&](int stage) {
        const uint32_t aB = sb + (uint32_t)stage * STG;
        const uint32_t bB = aB + 16384;
#pragma unroll
        for (int ks = 0; ks < 4; ++ks) {
            int kb = ks * 32 + kHalf;
            uint32_t af[4][4], bf2[2][4];
#pragma unroll
            for (int mi = 0; mi < 4; ++mi)
                ldsm4(af[mi], aB + SWZ((uint32_t)((aRowB + mi * 16) * 128 + kb)));
#pragma unroll
            for (int nj = 0; nj < 2; ++nj)
                ldsm4(bf2[nj], bB + SWZ((uint32_t)((bRowB + nj * 16) * 128 + kb)));
#pragma unroll
            for (int mi = 0; mi < 4; ++mi)
#pragma unroll
                for (int g = 0; g < 2; ++g)
#pragma unroll
                    for (int s = 0; s < 2; ++s)
                        mma16(d[mi][g * 2 + s], af[mi], bf2[g][s], bf2[g][s + 2]);
            if constexpr (PASSES == 3) {
                uint32_t al[4][4], bl[2][4];
#pragma unroll
                for (int nj = 0; nj < 2; ++nj)
                    ldsm4(bl[nj], aB + 32768 + SWZ((uint32_t)((bRowB + nj * 16) * 128 + kb)));
#pragma unroll
                for (int mi = 0; mi < 4; ++mi)
                    ldsm4(al[mi], aB + 49152 + SWZ((uint32_t)((aRowB + mi * 16) * 128 + kb)));
#pragma unroll
                for (int mi = 0; mi < 4; ++mi)
#pragma unroll
                    for (int g = 0; g < 2; ++g)
#pragma unroll
                        for (int s = 0; s < 2; ++s) {
                            mma16(d[mi][g * 2 + s], af[mi], bl[g][s], bl[g][s + 2]);   // hi*lo
                            mma16(d[mi][g * 2 + s], al[mi], bf2[g][s], bf2[g][s + 2]); // lo*hi
                        }
            }
        }
    };

    // ---- pipelined mainloop ----
#pragma unroll
    for (int s = 0; s < NST - 1; ++s)
        if (s < niter) issue(s);

    for (int it = 0; it < niter; ++it) {
        if (it + NST - 1 < niter) issue(it + NST - 1);
        int allow = min(niter, it + NST) - it - 1;   // pending groups allowed with group 'it' done
        if (allow >= 2)      cpa_wait<2>();
        else if (allow == 1) cpa_wait<1>();
        else                 cpa_wait<0>();
        __syncthreads();
        compute(it % NST);
        __syncthreads();
    }

    // ---- epilogue ----
    const int g4 = lane >> 2, t4 = lane & 3;
#pragma unroll
    for (int mi = 0; mi < 4; ++mi) {
#pragma unroll
        for (int hf = 0; hf < 2; ++hf) {
            int row = row0 + warp_m * 64 + mi * 16 + g4 + hf * 8;
#pragma unroll
            for (int nt = 0; nt < 4; ++nt) {
                int col = col0 + warp_n * 32 + nt * 8 + t4 * 2;
                size_t gi = (size_t)row * N + col;
                float vx = d[mi][nt][hf * 2 + 0];
                float vy = d[mi][nt][hf * 2 + 1];
                if (EPI == EPI_NONE) {
                    vx *= scale; vy *= scale;
                } else if (EPI == EPI_EXP) {
                    vx = expf(vx * scale); vy = expf(vy * scale);
                } else if (EPI == EPI_BG) {
                    float2 bv = *(const float2*)(bias + col);
                    vx = gelu_exact(vx + bv.x); vy = gelu_exact(vy + bv.y);
                } else { // EPI_BGR
                    float2 bv = *(const float2*)(bias + col);
                    float2 rv = *(const float2*)(res + gi);
                    vx = rv.x + gelu_exact(vx + bv.x);
                    vy = rv.y + gelu_exact(vy + bv.y);
                }
                if constexpr (OSPLIT) {
                    float hx, lx, hy, ly;
                    splitbf(vx, hx, lx); splitbf(vy, hy, ly);
                    *(uint32_t*)((bf16*)C + gi) = packbf(hx, hy);
                    *(uint32_t*)(Cl + gi) = packbf(lx, ly);
                } else if constexpr (sizeof(OT) == 4) {
                    *(float2*)((float*)C + gi) = make_float2(vx, vy);
                } else {
                    *(uint32_t*)((bf16*)C + gi) = packbf(vx, vy);
                }
            }
        }
    }
}

// ---------------- preprocessing ----------------
// fp32 -> bf16 hi (+lo) elementwise (n4 = count/4)
__global__ void conv_hl_kernel(const float* __restrict__ src, bf16* __restrict__ dh,
                               bf16* __restrict__ dl, size_t n4)
{
    size_t i = (size_t)blockIdx.x * 256 + threadIdx.x;
    if (i >= n4) return;
    float4 v = ((const float4*)src)[i];
    uint2 h, l;
    if (dl) {
        float h0,l0,h1,l1,h2,l2,h3,l3;
        splitbf(v.x,h0,l0); splitbf(v.y,h1,l1); splitbf(v.z,h2,l2); splitbf(v.w,h3,l3);
        h.x = packbf(h0,h1); h.y = packbf(h2,h3);
        l.x = packbf(l0,l1); l.y = packbf(l2,l3);
        ((uint2*)dh)[i] = h;
        ((uint2*)dl)[i] = l;
    } else {
        h.x = packbf(v.x,v.y); h.y = packbf(v.z,v.w);
        ((uint2*)dh)[i] = h;
    }
}

// fp32 [R][Cc] -> bf16 [Cc][R] hi (+lo)
__global__ void transpose_hl_kernel(const float* __restrict__ src, bf16* __restrict__ dh,
                                    bf16* __restrict__ dl, int R, int Cc)
{
    __shared__ float tile[32][33];
    const int r0 = blockIdx.x * 32;
    const int c0 = blockIdx.y * 32;
    const int x = threadIdx.x;
#pragma unroll
    for (int yy = threadIdx.y; yy < 32; yy += 8)
        tile[yy][x] = src[(size_t)(r0 + yy) * Cc + c0 + x];
    __syncthreads();
#pragma unroll
    for (int yy = threadIdx.y; yy < 32; yy += 8) {
        float v = tile[x][yy];
        size_t o = (size_t)(c0 + yy) * R + r0 + x;
        if (dl) {
            float h, l; splitbf(v, h, l);
            dh[o] = __float2bfloat16(h);
            dl[o] = __float2bfloat16(l);
        } else {
            dh[o] = __float2bfloat16(v);
        }
    }
}

// ---------------- split-K reductions ----------------
__global__ void reduce_blend_kernel(const float* __restrict__ part, const float* __restrict__ X,
                                    const float* __restrict__ invS, const float* __restrict__ alpha,
                                    float* __restrict__ X2, bf16* __restrict__ X2h,
                                    bf16* __restrict__ X2l, int nsp)
{
    size_t i = (size_t)blockIdx.x * 256 + threadIdx.x;
    const float4* p = (const float4*)part;
    const size_t stride = (size_t)NROWS * DDIM / 4;
    float4 s = p[i];
    for (int z = 1; z < nsp; ++z) {
        float4 t = p[i + (size_t)z * stride];
        s.x += t.x; s.y += t.y; s.z += t.z; s.w += t.w;
    }
    int row = (int)((i * 4) / DDIM);
    float rs = invS[row];
    float blend = 1.0f / (1.0f + expf(-alpha[0]));
    float4 xv = ((const float4*)X)[i];
    float4 o;
    o.x = blend * (s.x * rs) + (1.0f - blend) * xv.x;
    o.y = blend * (s.y * rs) + (1.0f - blend) * xv.y;
    o.z = blend * (s.z * rs) + (1.0f - blend) * xv.z;
    o.w = blend * (s.w * rs) + (1.0f - blend) * xv.w;
    ((float4*)X2)[i] = o;
    float h0,l0,h1,l1,h2,l2,h3,l3;
    splitbf(o.x,h0,l0); splitbf(o.y,h1,l1); splitbf(o.z,h2,l2); splitbf(o.w,h3,l3);
    ((uint2*)X2h)[i] = make_uint2(packbf(h0,h1), packbf(h2,h3));
    ((uint2*)X2l)[i] = make_uint2(packbf(l0,l1), packbf(l2,l3));
}

__global__ void reduce_rs_kernel(const float* __restrict__ part, const float* __restrict__ invA,
                                 bf16* __restrict__ Th, bf16* __restrict__ Tl, int nsp)
{
    size_t i = (size_t)blockIdx.x * 256 + threadIdx.x;
    const float4* p = (const float4*)part;
    const size_t stride = (size_t)NROWS * DDIM / 4;
    float4 s = p[i];
    for (int z = 1; z < nsp; ++z) {
        float4 t = p[i + (size_t)z * stride];
        s.x += t.x; s.y += t.y; s.z += t.z; s.w += t.w;
    }
    int row = (int)((i * 4) / DDIM);
    float rs = invA[row];
    s.x *= rs; s.y *= rs; s.z *= rs; s.w *= rs;
    float h0,l0,h1,l1,h2,l2,h3,l3;
    splitbf(s.x,h0,l0); splitbf(s.y,h1,l1); splitbf(s.z,h2,l2); splitbf(s.w,h3,l3);
    ((uint2*)Th)[i] = make_uint2(packbf(h0,h1), packbf(h2,h3));
    ((uint2*)Tl)[i] = make_uint2(packbf(l0,l1), packbf(l2,l3));
}

// ---------------- row sum -> inverse (bf16 source) ----------------
__global__ void rowsum_inv_bf16_kernel(const bf16* __restrict__ S, float* __restrict__ inv, int ncols)
{
    const int row = blockIdx.x;
    const __nv_bfloat162* p = (const __nv_bfloat162*)(S + (size_t)row * ncols);
    const int t = threadIdx.x;
    float s = 0.0f;
    for (int j = t; j < ncols / 2; j += 256) {
        float2 v = __bfloat1622float2(p[j]);
        s += v.x + v.y;
    }
    __shared__ float red[256];
    red[t] = s; __syncthreads();
    for (int off = 128; off > 0; off >>= 1) {
        if (t < off) red[t] += red[t + off];
        __syncthreads();
    }
    if (t == 0) inv[row] = 1.0f / red[0];
}

// ---------------- final head ----------------
__global__ void head_kernel(const float* __restrict__ h2, const float* __restrict__ W3,
                            const float* __restrict__ b3, float* __restrict__ out)
{
    const int row = blockIdx.x;
    const int t = threadIdx.x;   // 64 threads
    const float* hr = h2 + (size_t)row * H2DIM;

    float a0 = 0.f, a1 = 0.f, a2 = 0.f, a3 = 0.f;
    for (int k = t; k < H2DIM; k += 64) {
        const float hv = hr[k];
        a0 = fmaf(hv, W3[k * 4 + 0], a0);
        a1 = fmaf(hv, W3[k * 4 + 1], a1);
        a2 = fmaf(hv, W3[k * 4 + 2], a2);
        a3 = fmaf(hv, W3[k * 4 + 3], a3);
    }
    __shared__ float s0[64], s1[64], s2[64], s3[64];
    s0[t] = a0; s1[t] = a1; s2[t] = a2; s3[t] = a3;
    __syncthreads();
    for (int off = 32; off > 0; off >>= 1) {
        if (t < off) {
            s0[t] += s0[t + off]; s1[t] += s1[t + off];
            s2[t] += s2[t + off]; s3[t] += s3[t + off];
        }
        __syncthreads();
    }
    if (t == 0) {
        const float r0 = s0[0] + b3[0];
        const float r1 = s1[0] + b3[1];
        const float r2 = s2[0] + b3[2];
        const float r3 = s3[0] + b3[3];
        out[0 * NROWS + row] = r0;
        out[1 * NROWS + row] = softplus_stable(r1) + 1e-6f;
        out[2 * NROWS + row] = fminf(softplus_stable(r2), 28.0f) + 1.01f;
        out[3 * NROWS + row] = softplus_stable(r3) + 1e-6f;
    }
}

// ---------------- host side ----------------
template<typename T>
static T* sym(const void* s) {
    void* p = nullptr;
    cudaGetSymbolAddress(&p, (const void*)s);
    return (T*)p;
}

template<int PASSES, int EPI, bool OSPLIT, typename OT>
static void launch_gemm(const bf16* Ah, const bf16* Al, const bf16* Bh, const bf16* Bl,
                        const float* bias, const float* res, OT* C, bf16* Cl,
                        int N, int Ktot, int splits, float scale)
{
    int smemB = NST * ((PASSES == 1) ? 32768 : 65536);
    cudaFuncSetAttribute(bgemm<PASSES, EPI, OSPLIT, OT>,
                         cudaFuncAttributeMaxDynamicSharedMemorySize, smemB);
    dim3 grid(N / 128, NROWS / 128, splits);
    bgemm<PASSES, EPI, OSPLIT, OT><<<grid, 256, smemB>>>(
        Ah, Al, Bh, Bl, bias, res, C, Cl, N, Ktot, Ktot / splits, scale);
}

extern "C" void kernel_launch(void* const* d_in, const int* in_sizes, int n_in,
                              void* d_out, int out_size)
{
    const float* X      = (const float*)d_in[0];
    const float* ctx_k  = (const float*)d_in[1];
    const float* ctx_v  = (const float*)d_in[2];
    const float* Wq_hop = (const float*)d_in[3];
    const float* alpha  = (const float*)d_in[4];
    const float* Wq_mol = (const float*)d_in[5];
    const float* Wk_mol = (const float*)d_in[6];
    const float* Wg     = (const float*)d_in[7];
    const float* bg     = (const float*)d_in[8];
    const float* W1     = (const float*)d_in[9];
    const float* b1     = (const float*)d_in[10];
    const float* W2     = (const float*)d_in[11];
    const float* b2     = (const float*)d_in[12];
    const float* W3     = (const float*)d_in[13];
    const float* b3     = (const float*)d_in[14];
    float* out = (float*)d_out;

    bf16 *S = sym<bf16>(g_S), *Vt = sym<bf16>(g_Vt), *Kc = sym<bf16>(g_Kc);
    bf16 *Xh = sym<bf16>(g_Xh), *Xl = sym<bf16>(g_Xl), *Qb = sym<bf16>(g_Qb);
    bf16 *X2h = sym<bf16>(g_X2h), *X2l = sym<bf16>(g_X2l);
    bf16 *X2th = sym<bf16>(g_X2th), *X2tl = sym<bf16>(g_X2tl);
    bf16 *Qmh = sym<bf16>(g_Qmh), *Qml = sym<bf16>(g_Qml);
    bf16 *Kmh = sym<bf16>(g_Kmh), *Kml = sym<bf16>(g_Kml);
    bf16 *A2h = sym<bf16>(g_A2h), *A2l = sym<bf16>(g_A2l);
    bf16 *Th = sym<bf16>(g_Th), *Tl = sym<bf16>(g_Tl);
    bf16 *Hh = sym<bf16>(g_Hh), *Hl = sym<bf16>(g_Hl);
    bf16 *H1h = sym<bf16>(g_H1h), *H1l = sym<bf16>(g_H1l);
    bf16 *Wqh_h = sym<bf16>(g_Wqh_h), *Wqh_l = sym<bf16>(g_Wqh_l);
    bf16 *Wqm_h = sym<bf16>(g_Wqm_h), *Wqm_l = sym<bf16>(g_Wqm_l);
    bf16 *Wkm_h = sym<bf16>(g_Wkm_h), *Wkm_l = sym<bf16>(g_Wkm_l);
    bf16 *Wg_h = sym<bf16>(g_Wg_h), *Wg_l = sym<bf16>(g_Wg_l);
    bf16 *W1_h = sym<bf16>(g_W1_h), *W1_l = sym<bf16>(g_W1_l);
    bf16 *W2_h = sym<bf16>(g_W2_h), *W2_l = sym<bf16>(g_W2_l);
    float *X2 = sym<float>(g_X2), *H2 = sym<float>(g_H2);
    float *invS = sym<float>(g_invS), *invA = sym<float>(g_invA);
    float *part = sym<float>(g_part);

    const float inv_sqrt_dinner = 0.0625f;              // 1/sqrt(256)
    const float inv_sqrt_d = 0.036084391824351615f;     // 1/sqrt(768)
    const dim3 tb(32, 8);

    // ---- preprocessing: K-major bf16 (hi/lo) operands ----
    conv_hl_kernel<<<(NROWS * DDIM / 4 + 255) / 256, 256>>>(X, Xh, Xl, (size_t)NROWS * DDIM / 4);
    conv_hl_kernel<<<((size_t)MCTX * DINNER / 4 + 255) / 256, 256>>>(ctx_k, Kc, nullptr, (size_t)MCTX * DINNER / 4);
    transpose_hl_kernel<<<dim3(MCTX / 32, DDIM / 32), tb>>>(ctx_v, Vt, nullptr, MCTX, DDIM);
    transpose_hl_kernel<<<dim3(DDIM / 32, DINNER / 32), tb>>>(Wq_hop, Wqh_h, Wqh_l, DDIM, DINNER);
    transpose_hl_kernel<<<dim3(DDIM / 32, DDIM / 32), tb>>>(Wq_mol, Wqm_h, Wqm_l, DDIM, DDIM);
    transpose_hl_kernel<<<dim3(DDIM / 32, DDIM / 32), tb>>>(Wk_mol, Wkm_h, Wkm_l, DDIM, DDIM);
    transpose_hl_kernel<<<dim3(DDIM / 32, DDIM / 32), tb>>>(Wg, Wg_h, Wg_l, DDIM, DDIM);
    transpose_hl_kernel<<<dim3(DDIM / 32, H1DIM / 32), tb>>>(W1, W1_h, W1_l, DDIM, H1DIM);
    transpose_hl_kernel<<<dim3(H1DIM / 32, H2DIM / 32), tb>>>(W2, W2_h, W2_l, H1DIM, H2DIM);

    // 1. Q = X @ Wq_hop -> bf16                 (N=256, K=768)   split-3
    launch_gemm<3, EPI_NONE, false>(Xh, Xl, Wqh_h, Wqh_l, nullptr, nullptr,
                                    Qb, nullptr, DINNER, DDIM, 1, 1.0f);

    // 2. S = exp(Q @ ctx_k^T / 16) -> bf16      (N=32768, K=256) single
    launch_gemm<1, EPI_EXP, false>(Qb, nullptr, Kc, nullptr, nullptr, nullptr,
                                   S, nullptr, MCTX, DINNER, 1, inv_sqrt_dinner);

    // 3. invS = 1 / rowsum(S)
    rowsum_inv_bf16_kernel<<<NROWS, 256>>>(S, invS, MCTX);

    // 4. enriched partials = S @ Vt^T (split-K=8); X2 = blend*(invS*sum) + (1-blend)*X
    launch_gemm<1, EPI_NONE, false>(S, nullptr, Vt, nullptr, nullptr, nullptr,
                                    part, nullptr, DDIM, MCTX, 8, 1.0f);
    reduce_blend_kernel<<<NROWS * DDIM / 1024, 256>>>(part, X, invS, alpha, X2, X2h, X2l, 8);
    transpose_hl_kernel<<<dim3(NROWS / 32, DDIM / 32), tb>>>(X2, X2th, X2tl, NROWS, DDIM);

    // 5. Qm, Km                                  (N=768, K=768)  split-3
    launch_gemm<3, EPI_NONE, true>(X2h, X2l, Wqm_h, Wqm_l, nullptr, nullptr,
                                   Qmh, Qml, DDIM, DDIM, 1, 1.0f);
    launch_gemm<3, EPI_NONE, true>(X2h, X2l, Wkm_h, Wkm_l, nullptr, nullptr,
                                   Kmh, Kml, DDIM, DDIM, 1, 1.0f);

    // 6. A2 = exp(Qm @ Km^T / sqrt(768))         (N=4096, K=768) split-3
    launch_gemm<3, EPI_EXP, true>(Qmh, Qml, Kmh, Kml, nullptr, nullptr,
                                  A2h, A2l, NROWS, DDIM, 1, inv_sqrt_d);

    // 7. invA = 1 / rowsum(A2h)  (lo part: ~2^-9 of sum, negligible for 1/sum)
    rowsum_inv_bf16_kernel<<<NROWS, 256>>>(A2h, invA, NROWS);

    // 8. T partials = A2 @ X2 (split-K=4); T = invA*sum -> bf16 hi/lo
    launch_gemm<3, EPI_NONE, false>(A2h, A2l, X2th, X2tl, nullptr, nullptr,
                                    part, nullptr, DDIM, NROWS, 4, 1.0f);
    reduce_rs_kernel<<<NROWS * DDIM / 1024, 256>>>(part, invA, Th, Tl, 4);

    // 9. H = X2 + gelu(T @ Wg + bg)              (N=768, K=768)  split-3
    launch_gemm<3, EPI_BGR, true>(Th, Tl, Wg_h, Wg_l, bg, X2,
                                  Hh, Hl, DDIM, DDIM, 1, 1.0f);

    // 10. H1 = gelu(H @ W1 + b1)                 (N=512, K=768)  split-3
    launch_gemm<3, EPI_BG, true>(Hh, Hl, W1_h, W1_l, b1, nullptr,
                                 H1h, H1l, H1DIM, DDIM, 1, 1.0f);

    // 11. H2 = gelu(H1 @ W2 + b2) -> fp32        (N=256, K=512)  split-3
    launch_gemm<3, EPI_BG, false>(H1h, H1l, W2_h, W2_l, b2, nullptr,
                                  H2, nullptr, H2DIM, H1DIM, 1, 1.0f);

    // 12. head -> out (mu | v | a | b)
    head_kernel<<<NROWS, 64>>>(H2, W3, b3, out);

    (void)in_sizes; (void)n_in; (void)out_size;
}

// round 10
// speedup vs baseline: 9.4671x; 1.3096x over previous
#include <cuda_runtime.h>
#include <cuda_bf16.h>
#include <math.h>
#include <stdint.h>

// ---------------- problem constants ----------------
#define NROWS 4096
#define DDIM  768
#define DINNER 256
#define MCTX  32768
#define H1DIM 512
#define H2DIM 256

typedef __nv_bfloat16 bf16;

// ---------------- scratch (device globals; no allocation allowed) ----------------
__device__ bf16 g_S[(size_t)NROWS * MCTX];       // exp(logits) hopfield, bf16
__device__ bf16 g_Vt[(size_t)DDIM * MCTX];       // ctx_v^T bf16
__device__ bf16 g_Kc[(size_t)MCTX * DINNER];     // ctx_k bf16
__device__ bf16 g_Xh[(size_t)NROWS * DDIM];
__device__ bf16 g_Xl[(size_t)NROWS * DDIM];
__device__ bf16 g_Qb[(size_t)NROWS * DINNER];
__device__ bf16 g_X2h[(size_t)NROWS * DDIM];
__device__ bf16 g_X2th[(size_t)DDIM * NROWS];
__device__ bf16 g_Qmh[(size_t)NROWS * DDIM];
__device__ bf16 g_Kmh[(size_t)NROWS * DDIM];
__device__ bf16 g_A2h[(size_t)NROWS * NROWS];
__device__ bf16 g_Th[(size_t)NROWS * DDIM];
__device__ bf16 g_Hh[(size_t)NROWS * DDIM];
__device__ bf16 g_Hl[(size_t)NROWS * DDIM];
__device__ bf16 g_H1h[(size_t)NROWS * H1DIM];
__device__ bf16 g_H1l[(size_t)NROWS * H1DIM];
// pre-transposed weights
__device__ bf16 g_Wqh_h[(size_t)DINNER * DDIM];
__device__ bf16 g_Wqh_l[(size_t)DINNER * DDIM];
__device__ bf16 g_Wqm_h[(size_t)DDIM * DDIM];
__device__ bf16 g_Wkm_h[(size_t)DDIM * DDIM];
__device__ bf16 g_Wg_h[(size_t)DDIM * DDIM];
__device__ bf16 g_W1_h[(size_t)H1DIM * DDIM];
__device__ bf16 g_W1_l[(size_t)H1DIM * DDIM];
__device__ bf16 g_W2_h[(size_t)H2DIM * H1DIM];
__device__ bf16 g_W2_l[(size_t)H2DIM * H1DIM];
// fp32
__device__ float g_X2[(size_t)NROWS * DDIM];
__device__ float g_H2[(size_t)NROWS * H2DIM];
__device__ float g_invS[NROWS];
__device__ float g_invA[NROWS];
__device__ float g_part[(size_t)8 * NROWS * DDIM];

// ---------------- helpers ----------------
__device__ __forceinline__ uint32_t smem_u32(const void* p) {
    uint32_t a;
    asm("{ .reg .u64 t; cvta.to.shared.u64 t, %1; cvt.u32.u64 %0, t; }" : "=r"(a) : "l"(p));
    return a;
}
#define SWZ(off) ((off) ^ (((off) >> 3) & 0x70))

__device__ __forceinline__ uint32_t packbf(float x0, float x1) {
    uint32_t r;
    asm("cvt.rn.bf16x2.f32 %0, %1, %2;" : "=r"(r) : "f"(x1), "f"(x0));
    return r;
}
__device__ __forceinline__ void splitbf(float x, float& h, float& l) {
    h = __bfloat162float(__float2bfloat16(x));
    l = x - h;
}
__device__ __forceinline__ float gelu_exact(float x) {
    return 0.5f * x * (1.0f + erff(x * 0.70710678118654752f));
}
__device__ __forceinline__ float softplus_stable(float x) {
    return (x > 20.0f) ? x : log1pf(expf(x));
}

__device__ __forceinline__ void cpa16(uint32_t dst, const void* src) {
    asm volatile("cp.async.cg.shared.global [%0], [%1], 16;" :: "r"(dst), "l"(src));
}
__device__ __forceinline__ void cpa_commit() {
    asm volatile("cp.async.commit_group;" ::: "memory");
}
template<int N>
__device__ __forceinline__ void cpa_wait() {
    asm volatile("cp.async.wait_group %0;" :: "n"(N) : "memory");
}

__device__ __forceinline__ void ldsm4(uint32_t* r, uint32_t addr) {
    asm volatile("ldmatrix.sync.aligned.m8n8.x4.shared.b16 {%0,%1,%2,%3}, [%4];"
        : "=r"(r[0]), "=r"(r[1]), "=r"(r[2]), "=r"(r[3]) : "r"(addr));
}
__device__ __forceinline__ void mma16(float* d, const uint32_t* a, uint32_t b0, uint32_t b1) {
    asm volatile("mma.sync.aligned.m16n8k16.row.col.f32.bf16.bf16.f32 "
        "{%0,%1,%2,%3}, {%4,%5,%6,%7}, {%8,%9}, {%0,%1,%2,%3};"
        : "+f"(d[0]), "+f"(d[1]), "+f"(d[2]), "+f"(d[3])
        : "r"(a[0]), "r"(a[1]), "r"(a[2]), "r"(a[3]), "r"(b0), "r"(b1));
}

// ---------------- unified bf16 GEMM (all operands K-major bf16) ----------------
// C[4096,N] = epi(A @ B^T). PASSES=1: Ah.Bh   PASSES=3: Ah.Bh + Ah.Bl + Al.Bh
// 128x128x64 tiles, 8 warps (2m x 4n), m16n8k16 bf16 mma, cp.async 3-stage pipeline.
#define EPI_NONE 0
#define EPI_EXP 1          // exp(v*scale)
#define EPI_BG 2           // gelu(v + bias[c])
#define EPI_BGR 3          // res + gelu(v + bias[c])

#define NST 3

template<int PASSES, int EPI, bool OSPLIT, typename OT>
__global__ __launch_bounds__(256, PASSES == 1 ? 2 : 1)
void bgemm(const bf16* __restrict__ Ah, const bf16* __restrict__ Al,
           const bf16* __restrict__ Bh, const bf16* __restrict__ Bl,
           const float* __restrict__ bias, const float* __restrict__ res,
           OT* __restrict__ C, bf16* __restrict__ Cl,
           int N, int Ktot, int kLen, float scale)
{
    constexpr uint32_t STG = (PASSES == 1) ? 32768u : 65536u;
    extern __shared__ char smem[];
    const uint32_t sb = smem_u32(smem);
    const int tid = threadIdx.x;
    const int lane = tid & 31;
    const int wid = tid >> 5;
    const int warp_m = wid >> 2;
    const int warp_n = wid & 3;
    const int row0 = blockIdx.y * 128;
    const int col0 = blockIdx.x * 128;
    const int kOff = blockIdx.z * kLen;
    if (blockIdx.z) C += (size_t)blockIdx.z * NROWS * N;

    float d[4][4][4];
#pragma unroll
    for (int i = 0; i < 4; i++)
#pragma unroll
        for (int j = 0; j < 4; j++)
#pragma unroll
            for (int q = 0; q < 4; q++) d[i][j][q] = 0.0f;

    const int niter = kLen >> 6;

    auto issue = [&](int j) {
        const uint32_t sbase = sb + (uint32_t)(j % NST) * STG;
        const int k0 = kOff + j * 64;
#pragma unroll
        for (int l = 0; l < 4; ++l) {
            int c = tid + l * 256;
            int r = c >> 3, c16 = c & 7;
            uint32_t soff = SWZ((uint32_t)(r * 128 + c16 * 16));
            size_t ga = (size_t)(row0 + r) * Ktot + k0 + c16 * 8;
            size_t gb = (size_t)(col0 + r) * Ktot + k0 + c16 * 8;
            cpa16(sbase + soff, Ah + ga);
            cpa16(sbase + 16384 + soff, Bh + gb);
            if constexpr (PASSES == 3) {
                cpa16(sbase + 32768 + soff, Bl + gb);
                cpa16(sbase + 49152 + soff, Al + ga);
            }
        }
        cpa_commit();
    };

    const int lmat = lane >> 3;
    const int lrow = lane & 7;
    const int aRowB = warp_m * 64 + ((lmat & 1) << 3) + lrow;
    const int bRowB = warp_n * 32 + ((lmat & 1) << 3) + lrow;
    const int kHalf = (lmat >> 1) << 4;

    auto compute = [&](int stage) {
        const uint32_t aB = sb + (uint32_t)stage * STG;
        const uint32_t bB = aB + 16384;
#pragma unroll
        for (int ks = 0; ks < 4; ++ks) {
            int kb = ks * 32 + kHalf;
            uint32_t af[4][4], bf2[2][4];
#pragma unroll
            for (int mi = 0; mi < 4; ++mi)
                ldsm4(af[mi], aB + SWZ((uint32_t)((aRowB + mi * 16) * 128 + kb)));
#pragma unroll
            for (int nj = 0; nj < 2; ++nj)
                ldsm4(bf2[nj], bB + SWZ((uint32_t)((bRowB + nj * 16) * 128 + kb)));
#pragma unroll
            for (int mi = 0; mi < 4; ++mi)
#pragma unroll
                for (int g = 0; g < 2; ++g)
#pragma unroll
                    for (int s = 0; s < 2; ++s)
                        mma16(d[mi][g * 2 + s], af[mi], bf2[g][s], bf2[g][s + 2]);
            if constexpr (PASSES == 3) {
                uint32_t al[4][4], bl[2][4];
#pragma unroll
                for (int nj = 0; nj < 2; ++nj)
                    ldsm4(bl[nj], aB + 32768 + SWZ((uint32_t)((bRowB + nj * 16) * 128 + kb)));
#pragma unroll
                for (int mi = 0; mi < 4; ++mi)
                    ldsm4(al[mi], aB + 49152 + SWZ((uint32_t)((aRowB + mi * 16) * 128 + kb)));
#pragma unroll
                for (int mi = 0; mi < 4; ++mi)
#pragma unroll
                    for (int g = 0; g < 2; ++g)
#pragma unroll
                        for (int s = 0; s < 2; ++s) {
                            mma16(d[mi][g * 2 + s], af[mi], bl[g][s], bl[g][s + 2]);
                            mma16(d[mi][g * 2 + s], al[mi], bf2[g][s], bf2[g][s + 2]);
                        }
            }
        }
    };

#pragma unroll
    for (int s = 0; s < NST - 1; ++s)
        if (s < niter) issue(s);

    for (int it = 0; it < niter; ++it) {
        if (it + NST - 1 < niter) issue(it + NST - 1);
        int allow = min(niter, it + NST) - it - 1;
        if (allow >= 2)      cpa_wait<2>();
        else if (allow == 1) cpa_wait<1>();
        else                 cpa_wait<0>();
        __syncthreads();
        compute(it % NST);
        __syncthreads();
    }

    // ---- epilogue ----
    const int g4 = lane >> 2, t4 = lane & 3;
#pragma unroll
    for (int mi = 0; mi < 4; ++mi) {
#pragma unroll
        for (int hf = 0; hf < 2; ++hf) {
            int row = row0 + warp_m * 64 + mi * 16 + g4 + hf * 8;
#pragma unroll
            for (int nt = 0; nt < 4; ++nt) {
                int col = col0 + warp_n * 32 + nt * 8 + t4 * 2;
                size_t gi = (size_t)row * N + col;
                float vx = d[mi][nt][hf * 2 + 0];
                float vy = d[mi][nt][hf * 2 + 1];
                if (EPI == EPI_NONE) {
                    vx *= scale; vy *= scale;
                } else if (EPI == EPI_EXP) {
                    vx = expf(vx * scale); vy = expf(vy * scale);
                } else if (EPI == EPI_BG) {
                    float2 bv = *(const float2*)(bias + col);
                    vx = gelu_exact(vx + bv.x); vy = gelu_exact(vy + bv.y);
                } else { // EPI_BGR
                    float2 bv = *(const float2*)(bias + col);
                    float2 rv = *(const float2*)(res + gi);
                    vx = rv.x + gelu_exact(vx + bv.x);
                    vy = rv.y + gelu_exact(vy + bv.y);
                }
                if constexpr (OSPLIT) {
                    float hx, lx, hy, ly;
                    splitbf(vx, hx, lx); splitbf(vy, hy, ly);
                    *(uint32_t*)((bf16*)C + gi) = packbf(hx, hy);
                    *(uint32_t*)(Cl + gi) = packbf(lx, ly);
                } else if constexpr (sizeof(OT) == 4) {
                    *(float2*)((float*)C + gi) = make_float2(vx, vy);
                } else {
                    *(uint32_t*)((bf16*)C + gi) = packbf(vx, vy);
                }
            }
        }
    }
}

// ---------------- preprocessing ----------------
__global__ void conv_hl_kernel(const float* __restrict__ src, bf16* __restrict__ dh,
                               bf16* __restrict__ dl, size_t n4)
{
    size_t i = (size_t)blockIdx.x * 256 + threadIdx.x;
    if (i >= n4) return;
    float4 v = ((const float4*)src)[i];
    uint2 h, l;
    if (dl) {
        float h0,l0,h1,l1,h2,l2,h3,l3;
        splitbf(v.x,h0,l0); splitbf(v.y,h1,l1); splitbf(v.z,h2,l2); splitbf(v.w,h3,l3);
        h.x = packbf(h0,h1); h.y = packbf(h2,h3);
        l.x = packbf(l0,l1); l.y = packbf(l2,l3);
        ((uint2*)dh)[i] = h;
        ((uint2*)dl)[i] = l;
    } else {
        h.x = packbf(v.x,v.y); h.y = packbf(v.z,v.w);
        ((uint2*)dh)[i] = h;
    }
}

__global__ void transpose_hl_kernel(const float* __restrict__ src, bf16* __restrict__ dh,
                                    bf16* __restrict__ dl, int R, int Cc)
{
    __shared__ float tile[32][33];
    const int r0 = blockIdx.x * 32;
    const int c0 = blockIdx.y * 32;
    const int x = threadIdx.x;
#pragma unroll
    for (int yy = threadIdx.y; yy < 32; yy += 8)
        tile[yy][x] = src[(size_t)(r0 + yy) * Cc + c0 + x];
    __syncthreads();
#pragma unroll
    for (int yy = threadIdx.y; yy < 32; yy += 8) {
        float v = tile[x][yy];
        size_t o = (size_t)(c0 + yy) * R + r0 + x;
        if (dl) {
            float h, l; splitbf(v, h, l);
            dh[o] = __float2bfloat16(h);
            dl[o] = __float2bfloat16(l);
        } else {
            dh[o] = __float2bfloat16(v);
        }
    }
}

// ---------------- split-K reductions ----------------
__global__ void reduce_blend_kernel(const float* __restrict__ part, const float* __restrict__ X,
                                    const float* __restrict__ invS, const float* __restrict__ alpha,
                                    float* __restrict__ X2, bf16* __restrict__ X2h, int nsp)
{
    size_t i = (size_t)blockIdx.x * 256 + threadIdx.x;
    const float4* p = (const float4*)part;
    const size_t stride = (size_t)NROWS * DDIM / 4;
    float4 s = p[i];
    for (int z = 1; z < nsp; ++z) {
        float4 t = p[i + (size_t)z * stride];
        s.x += t.x; s.y += t.y; s.z += t.z; s.w += t.w;
    }
    int row = (int)((i * 4) / DDIM);
    float rs = invS[row];
    float blend = 1.0f / (1.0f + expf(-alpha[0]));
    float4 xv = ((const float4*)X)[i];
    float4 o;
    o.x = blend * (s.x * rs) + (1.0f - blend) * xv.x;
    o.y = blend * (s.y * rs) + (1.0f - blend) * xv.y;
    o.z = blend * (s.z * rs) + (1.0f - blend) * xv.z;
    o.w = blend * (s.w * rs) + (1.0f - blend) * xv.w;
    ((float4*)X2)[i] = o;
    ((uint2*)X2h)[i] = make_uint2(packbf(o.x, o.y), packbf(o.z, o.w));
}

__global__ void reduce_rs_kernel(const float* __restrict__ part, const float* __restrict__ invA,
                                 bf16* __restrict__ Th, int nsp)
{
    size_t i = (size_t)blockIdx.x * 256 + threadIdx.x;
    const float4* p = (const float4*)part;
    const size_t stride = (size_t)NROWS * DDIM / 4;
    float4 s = p[i];
    for (int z = 1; z < nsp; ++z) {
        float4 t = p[i + (size_t)z * stride];
        s.x += t.x; s.y += t.y; s.z += t.z; s.w += t.w;
    }
    int row = (int)((i * 4) / DDIM);
    float rs = invA[row];
    ((uint2*)Th)[i] = make_uint2(packbf(s.x * rs, s.y * rs), packbf(s.z * rs, s.w * rs));
}

// ---------------- row sum -> inverse (bf16 source) ----------------
__global__ void rowsum_inv_bf16_kernel(const bf16* __restrict__ S, float* __restrict__ inv, int ncols)
{
    const int row = blockIdx.x;
    const __nv_bfloat162* p = (const __nv_bfloat162*)(S + (size_t)row * ncols);
    const int t = threadIdx.x;
    float s = 0.0f;
    for (int j = t; j < ncols / 2; j += 256) {
        float2 v = __bfloat1622float2(p[j]);
        s += v.x + v.y;
    }
    __shared__ float red[256];
    red[t] = s; __syncthreads();
    for (int off = 128; off > 0; off >>= 1) {
        if (t < off) red[t] += red[t + off];
        __syncthreads();
    }
    if (t == 0) inv[row] = 1.0f / red[0];
}

// ---------------- final head ----------------
__global__ void head_kernel(const float* __restrict__ h2, const float* __restrict__ W3,
                            const float* __restrict__ b3, float* __restrict__ out)
{
    const int row = blockIdx.x;
    const int t = threadIdx.x;
    const float* hr = h2 + (size_t)row * H2DIM;

    float a0 = 0.f, a1 = 0.f, a2 = 0.f, a3 = 0.f;
    for (int k = t; k < H2DIM; k += 64) {
        const float hv = hr[k];
        a0 = fmaf(hv, W3[k * 4 + 0], a0);
        a1 = fmaf(hv, W3[k * 4 + 1], a1);
        a2 = fmaf(hv, W3[k * 4 + 2], a2);
        a3 = fmaf(hv, W3[k * 4 + 3], a3);
    }
    __shared__ float s0[64], s1[64], s2[64], s3[64];
    s0[t] = a0; s1[t] = a1; s2[t] = a2; s3[t] = a3;
    __syncthreads();
    for (int off = 32; off > 0; off >>= 1) {
        if (t < off) {
            s0[t] += s0[t + off]; s1[t] += s1[t + off];
            s2[t] += s2[t + off]; s3[t] += s3[t + off];
        }
        __syncthreads();
    }
    if (t == 0) {
        const float r0 = s0[0] + b3[0];
        const float r1 = s1[0] + b3[1];
        const float r2 = s2[0] + b3[2];
        const float r3 = s3[0] + b3[3];
        out[0 * NROWS + row] = r0;
        out[1 * NROWS + row] = softplus_stable(r1) + 1e-6f;
        out[2 * NROWS + row] = fminf(softplus_stable(r2), 28.0f) + 1.01f;
        out[3 * NROWS + row] = softplus_stable(r3) + 1e-6f;
    }
}

// ---------------- host side ----------------
template<typename T>
static T* sym(const void* s) {
    void* p = nullptr;
    cudaGetSymbolAddress(&p, (const void*)s);
    return (T*)p;
}

template<int PASSES, int EPI, bool OSPLIT, typename OT>
static void launch_gemm(const bf16* Ah, const bf16* Al, const bf16* Bh, const bf16* Bl,
                        const float* bias, const float* res, OT* C, bf16* Cl,
                        int N, int Ktot, int splits, float scale)
{
    int smemB = NST * ((PASSES == 1) ? 32768 : 65536);
    cudaFuncSetAttribute(bgemm<PASSES, EPI, OSPLIT, OT>,
                         cudaFuncAttributeMaxDynamicSharedMemorySize, smemB);
    dim3 grid(N / 128, NROWS / 128, splits);
    bgemm<PASSES, EPI, OSPLIT, OT><<<grid, 256, smemB>>>(
        Ah, Al, Bh, Bl, bias, res, C, Cl, N, Ktot, Ktot / splits, scale);
}

extern "C" void kernel_launch(void* const* d_in, const int* in_sizes, int n_in,
                              void* d_out, int out_size)
{
    const float* X      = (const float*)d_in[0];
    const float* ctx_k  = (const float*)d_in[1];
    const float* ctx_v  = (const float*)d_in[2];
    const float* Wq_hop = (const float*)d_in[3];
    const float* alpha  = (const float*)d_in[4];
    const float* Wq_mol = (const float*)d_in[5];
    const float* Wk_mol = (const float*)d_in[6];
    const float* Wg     = (const float*)d_in[7];
    const float* bg     = (const float*)d_in[8];
    const float* W1     = (const float*)d_in[9];
    const float* b1     = (const float*)d_in[10];
    const float* W2     = (const float*)d_in[11];
    const float* b2     = (const float*)d_in[12];
    const float* W3     = (const float*)d_in[13];
    const float* b3     = (const float*)d_in[14];
    float* out = (float*)d_out;

    bf16 *S = sym<bf16>(g_S), *Vt = sym<bf16>(g_Vt), *Kc = sym<bf16>(g_Kc);
    bf16 *Xh = sym<bf16>(g_Xh), *Xl = sym<bf16>(g_Xl), *Qb = sym<bf16>(g_Qb);
    bf16 *X2h = sym<bf16>(g_X2h), *X2th = sym<bf16>(g_X2th);
    bf16 *Qmh = sym<bf16>(g_Qmh), *Kmh = sym<bf16>(g_Kmh);
    bf16 *A2h = sym<bf16>(g_A2h), *Th = sym<bf16>(g_Th);
    bf16 *Hh = sym<bf16>(g_Hh), *Hl = sym<bf16>(g_Hl);
    bf16 *H1h = sym<bf16>(g_H1h), *H1l = sym<bf16>(g_H1l);
    bf16 *Wqh_h = sym<bf16>(g_Wqh_h), *Wqh_l = sym<bf16>(g_Wqh_l);
    bf16 *Wqm_h = sym<bf16>(g_Wqm_h), *Wkm_h = sym<bf16>(g_Wkm_h);
    bf16 *Wg_h = sym<bf16>(g_Wg_h);
    bf16 *W1_h = sym<bf16>(g_W1_h), *W1_l = sym<bf16>(g_W1_l);
    bf16 *W2_h = sym<bf16>(g_W2_h), *W2_l = sym<bf16>(g_W2_l);
    float *X2 = sym<float>(g_X2), *H2 = sym<float>(g_H2);
    float *invS = sym<float>(g_invS), *invA = sym<float>(g_invA);
    float *part = sym<float>(g_part);

    const float inv_sqrt_dinner = 0.0625f;              // 1/sqrt(256)
    const float inv_sqrt_d = 0.036084391824351615f;     // 1/sqrt(768)
    const dim3 tb(32, 8);

    // ---- preprocessing: K-major bf16 operands ----
    conv_hl_kernel<<<(NROWS * DDIM / 4 + 255) / 256, 256>>>(X, Xh, Xl, (size_t)NROWS * DDIM / 4);
    conv_hl_kernel<<<((size_t)MCTX * DINNER / 4 + 255) / 256, 256>>>(ctx_k, Kc, nullptr, (size_t)MCTX * DINNER / 4);
    transpose_hl_kernel<<<dim3(MCTX / 32, DDIM / 32), tb>>>(ctx_v, Vt, nullptr, MCTX, DDIM);
    transpose_hl_kernel<<<dim3(DDIM / 32, DINNER / 32), tb>>>(Wq_hop, Wqh_h, Wqh_l, DDIM, DINNER);
    transpose_hl_kernel<<<dim3(DDIM / 32, DDIM / 32), tb>>>(Wq_mol, Wqm_h, nullptr, DDIM, DDIM);
    transpose_hl_kernel<<<dim3(DDIM / 32, DDIM / 32), tb>>>(Wk_mol, Wkm_h, nullptr, DDIM, DDIM);
    transpose_hl_kernel<<<dim3(DDIM / 32, DDIM / 32), tb>>>(Wg, Wg_h, nullptr, DDIM, DDIM);
    transpose_hl_kernel<<<dim3(DDIM / 32, H1DIM / 32), tb>>>(W1, W1_h, W1_l, DDIM, H1DIM);
    transpose_hl_kernel<<<dim3(H1DIM / 32, H2DIM / 32), tb>>>(W2, W2_h, W2_l, H1DIM, H2DIM);

    // 1. Q = X @ Wq_hop -> bf16                 (N=256, K=768)   split-3 (feeds output path via X2)
    launch_gemm<3, EPI_NONE, false>(Xh, Xl, Wqh_h, Wqh_l, nullptr, nullptr,
                                    Qb, nullptr, DINNER, DDIM, 1, 1.0f);

    // 2. S = exp(Q @ ctx_k^T / 16) -> bf16      (N=32768, K=256) single
    launch_gemm<1, EPI_EXP, false>(Qb, nullptr, Kc, nullptr, nullptr, nullptr,
                                   S, nullptr, MCTX, DINNER, 1, inv_sqrt_dinner);

    // 3. invS = 1 / rowsum(S)
    rowsum_inv_bf16_kernel<<<NROWS, 256>>>(S, invS, MCTX);

    // 4. enriched partials = S @ Vt^T (split-K=8); X2 = blend*(invS*sum) + (1-blend)*X
    launch_gemm<1, EPI_NONE, false>(S, nullptr, Vt, nullptr, nullptr, nullptr,
                                    part, nullptr, DDIM, MCTX, 8, 1.0f);
    reduce_blend_kernel<<<NROWS * DDIM / 1024, 256>>>(part, X, invS, alpha, X2, X2h, 8);
    transpose_hl_kernel<<<dim3(NROWS / 32, DDIM / 32), tb>>>(X2, X2th, nullptr, NROWS, DDIM);

    // 5. Qm, Km  (N=768, K=768)  single — error damped ~50x via T-smallness + residual
    launch_gemm<1, EPI_NONE, false>(X2h, nullptr, Wqm_h, nullptr, nullptr, nullptr,
                                    Qmh, nullptr, DDIM, DDIM, 1, 1.0f);
    launch_gemm<1, EPI_NONE, false>(X2h, nullptr, Wkm_h, nullptr, nullptr, nullptr,
                                    Kmh, nullptr, DDIM, DDIM, 1, 1.0f);

    // 6. A2 = exp(Qm @ Km^T / sqrt(768)) -> bf16 (N=4096, K=768) single
    launch_gemm<1, EPI_EXP, false>(Qmh, nullptr, Kmh, nullptr, nullptr, nullptr,
                                   A2h, nullptr, NROWS, DDIM, 1, inv_sqrt_d);

    // 7. invA = 1 / rowsum(A2)
    rowsum_inv_bf16_kernel<<<NROWS, 256>>>(A2h, invA, NROWS);

    // 8. T partials = A2 @ X2 (split-K=4); T = invA*sum -> bf16   single
    launch_gemm<1, EPI_NONE, false>(A2h, nullptr, X2th, nullptr, nullptr, nullptr,
                                    part, nullptr, DDIM, NROWS, 4, 1.0f);
    reduce_rs_kernel<<<NROWS * DDIM / 1024, 256>>>(part, invA, Th, 4);

    // 9. H = X2 + gelu(T @ Wg + bg)  (N=768, K=768)  single; output split hi/lo for G10
    launch_gemm<1, EPI_BGR, true>(Th, nullptr, Wg_h, nullptr, bg, X2,
                                  Hh, Hl, DDIM, DDIM, 1, 1.0f);

    // 10. H1 = gelu(H @ W1 + b1)  (N=512, K=768)  split-3 (undamped output path)
    launch_gemm<3, EPI_BG, true>(Hh, Hl, W1_h, W1_l, b1, nullptr,
                                 H1h, H1l, H1DIM, DDIM, 1, 1.0f);

    // 11. H2 = gelu(H1 @ W2 + b2) -> fp32  (N=256, K=512)  split-3
    launch_gemm<3, EPI_BG, false>(H1h, H1l, W2_h, W2_l, b2, nullptr,
                                  H2, nullptr, H2DIM, H1DIM, 1, 1.0f);

    // 12. head -> out (mu | v | a | b)
    head_kernel<<<NROWS, 64>>>(H2, W3, b3, out);

    (void)in_sizes; (void)n_in; (void)out_size;
}

// round 11
// speedup vs baseline: 9.7825x; 1.0333x over previous
#include <cuda_runtime.h>
#include <cuda_bf16.h>
#include <math.h>
#include <stdint.h>

// ---------------- problem constants ----------------
#define NROWS 4096
#define DDIM  768
#define DINNER 256
#define MCTX  32768
#define H1DIM 512
#define H2DIM 256

typedef __nv_bfloat16 bf16;

// ---------------- scratch (device globals; no allocation allowed) ----------------
__device__ bf16 g_S[(size_t)NROWS * MCTX];
__device__ bf16 g_Vt[(size_t)DDIM * MCTX];
__device__ bf16 g_Kc[(size_t)MCTX * DINNER];
__device__ bf16 g_Xh[(size_t)NROWS * DDIM];
__device__ bf16 g_Xl[(size_t)NROWS * DDIM];
__device__ bf16 g_Qb[(size_t)NROWS * DINNER];
__device__ bf16 g_X2h[(size_t)NROWS * DDIM];
__device__ bf16 g_X2th[(size_t)DDIM * NROWS];
__device__ bf16 g_Qmh[(size_t)NROWS * DDIM];
__device__ bf16 g_Kmh[(size_t)NROWS * DDIM];
__device__ bf16 g_A2h[(size_t)NROWS * NROWS];
__device__ bf16 g_Th[(size_t)NROWS * DDIM];
__device__ bf16 g_Hh[(size_t)NROWS * DDIM];
__device__ bf16 g_Hl[(size_t)NROWS * DDIM];
__device__ bf16 g_H1h[(size_t)NROWS * H1DIM];
__device__ bf16 g_H1l[(size_t)NROWS * H1DIM];
// pre-transposed weights
__device__ bf16 g_Wqh_h[(size_t)DINNER * DDIM];
__device__ bf16 g_Wqh_l[(size_t)DINNER * DDIM];
__device__ bf16 g_Wqm_h[(size_t)DDIM * DDIM];
__device__ bf16 g_Wkm_h[(size_t)DDIM * DDIM];
__device__ bf16 g_Wg_h[(size_t)DDIM * DDIM];
__device__ bf16 g_W1_h[(size_t)H1DIM * DDIM];
__device__ bf16 g_W1_l[(size_t)H1DIM * DDIM];
__device__ bf16 g_W2_h[(size_t)H2DIM * H1DIM];
__device__ bf16 g_W2_l[(size_t)H2DIM * H1DIM];
// fp32
__device__ float g_X2[(size_t)NROWS * DDIM];
__device__ float g_H2[(size_t)NROWS * H2DIM];
__device__ float g_invS[NROWS];
__device__ float g_invA[NROWS];
__device__ float g_part[(size_t)8 * NROWS * DDIM];
__device__ float g_psum[(size_t)256 * NROWS];   // per-tile row partial sums (max 256 x-tiles)

// ---------------- helpers ----------------
__device__ __forceinline__ uint32_t smem_u32(const void* p) {
    uint32_t a;
    asm("{ .reg .u64 t; cvta.to.shared.u64 t, %1; cvt.u32.u64 %0, t; }" : "=r"(a) : "l"(p));
    return a;
}
#define SWZ(off) ((off) ^ (((off) >> 3) & 0x70))

__device__ __forceinline__ uint32_t packbf(float x0, float x1) {
    uint32_t r;
    asm("cvt.rn.bf16x2.f32 %0, %1, %2;" : "=r"(r) : "f"(x1), "f"(x0));
    return r;
}
__device__ __forceinline__ void splitbf(float x, float& h, float& l) {
    h = __bfloat162float(__float2bfloat16(x));
    l = x - h;
}
__device__ __forceinline__ float gelu_exact(float x) {
    return 0.5f * x * (1.0f + erff(x * 0.70710678118654752f));
}
__device__ __forceinline__ float softplus_stable(float x) {
    return (x > 20.0f) ? x : log1pf(expf(x));
}

__device__ __forceinline__ void cpa16(uint32_t dst, const void* src) {
    asm volatile("cp.async.cg.shared.global [%0], [%1], 16;" :: "r"(dst), "l"(src));
}
__device__ __forceinline__ void cpa_commit() {
    asm volatile("cp.async.commit_group;" ::: "memory");
}
template<int N>
__device__ __forceinline__ void cpa_wait() {
    asm volatile("cp.async.wait_group %0;" :: "n"(N) : "memory");
}

__device__ __forceinline__ void ldsm4(uint32_t* r, uint32_t addr) {
    asm volatile("ldmatrix.sync.aligned.m8n8.x4.shared.b16 {%0,%1,%2,%3}, [%4];"
        : "=r"(r[0]), "=r"(r[1]), "=r"(r[2]), "=r"(r[3]) : "r"(addr));
}
__device__ __forceinline__ void mma16(float* d, const uint32_t* a, uint32_t b0, uint32_t b1) {
    asm volatile("mma.sync.aligned.m16n8k16.row.col.f32.bf16.bf16.f32 "
        "{%0,%1,%2,%3}, {%4,%5,%6,%7}, {%8,%9}, {%0,%1,%2,%3};"
        : "+f"(d[0]), "+f"(d[1]), "+f"(d[2]), "+f"(d[3])
        : "r"(a[0]), "r"(a[1]), "r"(a[2]), "r"(a[3]), "r"(b0), "r"(b1));
}

// ---------------- unified bf16 GEMM ----------------
// C[4096,N] = epi(A @ B^T), K-major bf16 operands.
// 128x128x64 tiles, 4 warps (2m x 2n), warp tile 64x64, m16n8k16 bf16 mma.
// PASSES=1: Ah.Bh   PASSES=3: Ah.Bh + Ah.Bl + Al.Bh
// EPI_EXP additionally writes per-tile row sums to psum[blockIdx.x*4096 + row].
#define EPI_NONE 0
#define EPI_EXP 1
#define EPI_BG 2
#define EPI_BGR 3

#define NST 3

template<int PASSES, int EPI, bool OSPLIT, typename OT>
__global__ __launch_bounds__(128, PASSES == 1 ? 2 : 1)
void bgemm(const bf16* __restrict__ Ah, const bf16* __restrict__ Al,
           const bf16* __restrict__ Bh, const bf16* __restrict__ Bl,
           const float* __restrict__ bias, const float* __restrict__ res,
           OT* __restrict__ C, bf16* __restrict__ Cl, float* __restrict__ psum,
           int N, int Ktot, int kLen, float scale)
{
    constexpr uint32_t STG = (PASSES == 1) ? 32768u : 65536u;
    extern __shared__ char smem[];
    const uint32_t sb = smem_u32(smem);
    const int tid = threadIdx.x;
    const int lane = tid & 31;
    const int wid = tid >> 5;
    const int warp_m = wid >> 1;     // 0..1 (64 rows)
    const int warp_n = wid & 1;      // 0..1 (64 cols)
    const int row0 = blockIdx.y * 128;
    const int col0 = blockIdx.x * 128;
    const int kOff = blockIdx.z * kLen;
    if (blockIdx.z) C += (size_t)blockIdx.z * NROWS * N;

    float d[4][8][4];
#pragma unroll
    for (int i = 0; i < 4; i++)
#pragma unroll
        for (int j = 0; j < 8; j++)
#pragma unroll
            for (int q = 0; q < 4; q++) d[i][j][q] = 0.0f;

    const int niter = kLen >> 6;

    auto issue = [&](int j) {
        const uint32_t sbase = sb + (uint32_t)(j % NST) * STG;
        const int k0 = kOff + j * 64;
#pragma unroll
        for (int l = 0; l < 8; ++l) {
            int c = tid + l * 128;           // 0..1023
            int r = c >> 3, c16 = c & 7;
            uint32_t soff = SWZ((uint32_t)(r * 128 + c16 * 16));
            size_t ga = (size_t)(row0 + r) * Ktot + k0 + c16 * 8;
            size_t gb = (size_t)(col0 + r) * Ktot + k0 + c16 * 8;
            cpa16(sbase + soff, Ah + ga);
            cpa16(sbase + 16384 + soff, Bh + gb);
            if constexpr (PASSES == 3) {
                cpa16(sbase + 32768 + soff, Bl + gb);
                cpa16(sbase + 49152 + soff, Al + ga);
            }
        }
        cpa_commit();
    };

    const int lmat = lane >> 3;
    const int lrow = lane & 7;
    const int aRowB = warp_m * 64 + ((lmat & 1) << 3) + lrow;
    const int bRowB = warp_n * 64 + ((lmat & 1) << 3) + lrow;
    const int kHalf = (lmat >> 1) << 4;

    auto compute = [&](int stage) {
        const uint32_t aB = sb + (uint32_t)stage * STG;
        const uint32_t bB = aB + 16384;
#pragma unroll
        for (int ks = 0; ks < 4; ++ks) {
            int kb = ks * 32 + kHalf;
            uint32_t af[4][4], bf2[4][4];
#pragma unroll
            for (int mi = 0; mi < 4; ++mi)
                ldsm4(af[mi], aB + SWZ((uint32_t)((aRowB + mi * 16) * 128 + kb)));
#pragma unroll
            for (int nj = 0; nj < 4; ++nj)
                ldsm4(bf2[nj], bB + SWZ((uint32_t)((bRowB + nj * 16) * 128 + kb)));
#pragma unroll
            for (int mi = 0; mi < 4; ++mi)
#pragma unroll
                for (int nj = 0; nj < 4; ++nj)
#pragma unroll
                    for (int s = 0; s < 2; ++s)
                        mma16(d[mi][nj * 2 + s], af[mi], bf2[nj][s], bf2[nj][s + 2]);
            if constexpr (PASSES == 3) {
                uint32_t al[4][4], bl[4][4];
#pragma unroll
                for (int nj = 0; nj < 4; ++nj)
                    ldsm4(bl[nj], aB + 32768 + SWZ((uint32_t)((bRowB + nj * 16) * 128 + kb)));
#pragma unroll
                for (int mi = 0; mi < 4; ++mi)
                    ldsm4(al[mi], aB + 49152 + SWZ((uint32_t)((aRowB + mi * 16) * 128 + kb)));
#pragma unroll
                for (int mi = 0; mi < 4; ++mi)
#pragma unroll
                    for (int nj = 0; nj < 4; ++nj)
#pragma unroll
                        for (int s = 0; s < 2; ++s) {
                            mma16(d[mi][nj * 2 + s], af[mi], bl[nj][s], bl[nj][s + 2]);
                            mma16(d[mi][nj * 2 + s], al[mi], bf2[nj][s], bf2[nj][s + 2]);
                        }
            }
        }
    };

#pragma unroll
    for (int s = 0; s < NST - 1; ++s)
        if (s < niter) issue(s);

    for (int it = 0; it < niter; ++it) {
        if (it + NST - 1 < niter) issue(it + NST - 1);
        int allow = min(niter, it + NST) - it - 1;
        if (allow >= 2)      cpa_wait<2>();
        else if (allow == 1) cpa_wait<1>();
        else                 cpa_wait<0>();
        __syncthreads();
        compute(it % NST);
        __syncthreads();
    }

    // ---- epilogue ----
    const int g4 = lane >> 2, t4 = lane & 3;
    float rsum[4][2];
    if (EPI == EPI_EXP) {
#pragma unroll
        for (int mi = 0; mi < 4; ++mi) { rsum[mi][0] = 0.0f; rsum[mi][1] = 0.0f; }
    }
#pragma unroll
    for (int mi = 0; mi < 4; ++mi) {
#pragma unroll
        for (int hf = 0; hf < 2; ++hf) {
            int row = row0 + warp_m * 64 + mi * 16 + g4 + hf * 8;
#pragma unroll
            for (int nt = 0; nt < 8; ++nt) {
                int col = col0 + warp_n * 64 + nt * 8 + t4 * 2;
                size_t gi = (size_t)row * N + col;
                float vx = d[mi][nt][hf * 2 + 0];
                float vy = d[mi][nt][hf * 2 + 1];
                if (EPI == EPI_NONE) {
                    vx *= scale; vy *= scale;
                } else if (EPI == EPI_EXP) {
                    vx = expf(vx * scale); vy = expf(vy * scale);
                    rsum[mi][hf] += vx + vy;
                } else if (EPI == EPI_BG) {
                    float2 bv = *(const float2*)(bias + col);
                    vx = gelu_exact(vx + bv.x); vy = gelu_exact(vy + bv.y);
                } else { // EPI_BGR
                    float2 bv = *(const float2*)(bias + col);
                    float2 rv = *(const float2*)(res + gi);
                    vx = rv.x + gelu_exact(vx + bv.x);
                    vy = rv.y + gelu_exact(vy + bv.y);
                }
                if constexpr (OSPLIT) {
                    float hx, lx, hy, ly;
                    splitbf(vx, hx, lx); splitbf(vy, hy, ly);
                    *(uint32_t*)((bf16*)C + gi) = packbf(hx, hy);
                    *(uint32_t*)(Cl + gi) = packbf(lx, ly);
                } else if constexpr (sizeof(OT) == 4) {
                    *(float2*)((float*)C + gi) = make_float2(vx, vy);
                } else {
                    *(uint32_t*)((bf16*)C + gi) = packbf(vx, vy);
                }
            }
        }
    }

    if (EPI == EPI_EXP) {
        // reduce across t4 subgroup (lanes 4g..4g+3 share a row)
#pragma unroll
        for (int mi = 0; mi < 4; ++mi)
#pragma unroll
            for (int hf = 0; hf < 2; ++hf) {
                float v = rsum[mi][hf];
                v += __shfl_xor_sync(0xffffffffu, v, 1);
                v += __shfl_xor_sync(0xffffffffu, v, 2);
                rsum[mi][hf] = v;
            }
        float* psmem = (float*)smem;   // [128 rows][2 warp_n] — stages are dead here
        if (t4 == 0) {
#pragma unroll
            for (int mi = 0; mi < 4; ++mi)
#pragma unroll
                for (int hf = 0; hf < 2; ++hf) {
                    int rloc = warp_m * 64 + mi * 16 + hf * 8 + g4;
                    psmem[rloc * 2 + warp_n] = rsum[mi][hf];
                }
        }
        __syncthreads();
        // one partial per row per tile (deterministic)
        psum[(size_t)blockIdx.x * NROWS + row0 + tid] = psmem[tid * 2] + psmem[tid * 2 + 1];
    }
}

// ---------------- combine row partials -> inverse ----------------
__global__ void rowsum_combine_kernel(const float* __restrict__ psum, float* __restrict__ inv, int ntiles)
{
    int row = blockIdx.x * 256 + threadIdx.x;
    if (row >= NROWS) return;
    float s = 0.0f;
    for (int x = 0; x < ntiles; ++x) s += psum[(size_t)x * NROWS + row];
    inv[row] = 1.0f / s;
}

// ---------------- preprocessing ----------------
__global__ void conv_hl_kernel(const float* __restrict__ src, bf16* __restrict__ dh,
                               bf16* __restrict__ dl, size_t n4)
{
    size_t i = (size_t)blockIdx.x * 256 + threadIdx.x;
    if (i >= n4) return;
    float4 v = ((const float4*)src)[i];
    uint2 h, l;
    if (dl) {
        float h0,l0,h1,l1,h2,l2,h3,l3;
        splitbf(v.x,h0,l0); splitbf(v.y,h1,l1); splitbf(v.z,h2,l2); splitbf(v.w,h3,l3);
        h.x = packbf(h0,h1); h.y = packbf(h2,h3);
        l.x = packbf(l0,l1); l.y = packbf(l2,l3);
        ((uint2*)dh)[i] = h;
        ((uint2*)dl)[i] = l;
    } else {
        h.x = packbf(v.x,v.y); h.y = packbf(v.z,v.w);
        ((uint2*)dh)[i] = h;
    }
}

__global__ void transpose_hl_kernel(const float* __restrict__ src, bf16* __restrict__ dh,
                                    bf16* __restrict__ dl, int R, int Cc)
{
    __shared__ float tile[32][33];
    const int r0 = blockIdx.x * 32;
    const int c0 = blockIdx.y * 32;
    const int x = threadIdx.x;
#pragma unroll
    for (int yy = threadIdx.y; yy < 32; yy += 8)
        tile[yy][x] = src[(size_t)(r0 + yy) * Cc + c0 + x];
    __syncthreads();
#pragma unroll
    for (int yy = threadIdx.y; yy < 32; yy += 8) {
        float v = tile[x][yy];
        size_t o = (size_t)(c0 + yy) * R + r0 + x;
        if (dl) {
            float h, l; splitbf(v, h, l);
            dh[o] = __float2bfloat16(h);
            dl[o] = __float2bfloat16(l);
        } else {
            dh[o] = __float2bfloat16(v);
        }
    }
}

// ---------------- split-K reductions ----------------
__global__ void reduce_blend_kernel(const float* __restrict__ part, const float* __restrict__ X,
                                    const float* __restrict__ invS, const float* __restrict__ alpha,
                                    float* __restrict__ X2, bf16* __restrict__ X2h, int nsp)
{
    size_t i = (size_t)blockIdx.x * 256 + threadIdx.x;
    const float4* p = (const float4*)part;
    const size_t stride = (size_t)NROWS * DDIM / 4;
    float4 s = p[i];
    for (int z = 1; z < nsp; ++z) {
        float4 t = p[i + (size_t)z * stride];
        s.x += t.x; s.y += t.y; s.z += t.z; s.w += t.w;
    }
    int row = (int)((i * 4) / DDIM);
    float rs = invS[row];
    float blend = 1.0f / (1.0f + expf(-alpha[0]));
    float4 xv = ((const float4*)X)[i];
    float4 o;
    o.x = blend * (s.x * rs) + (1.0f - blend) * xv.x;
    o.y = blend * (s.y * rs) + (1.0f - blend) * xv.y;
    o.z = blend * (s.z * rs) + (1.0f - blend) * xv.z;
    o.w = blend * (s.w * rs) + (1.0f - blend) * xv.w;
    ((float4*)X2)[i] = o;
    ((uint2*)X2h)[i] = make_uint2(packbf(o.x, o.y), packbf(o.z, o.w));
}

__global__ void reduce_rs_kernel(const float* __restrict__ part, const float* __restrict__ invA,
                                 bf16* __restrict__ Th, int nsp)
{
    size_t i = (size_t)blockIdx.x * 256 + threadIdx.x;
    const float4* p = (const float4*)part;
    const size_t stride = (size_t)NROWS * DDIM / 4;
    float4 s = p[i];
    for (int z = 1; z < nsp; ++z) {
        float4 t = p[i + (size_t)z * stride];
        s.x += t.x; s.y += t.y; s.z += t.z; s.w += t.w;
    }
    int row = (int)((i * 4) / DDIM);
    float rs = invA[row];
    ((uint2*)Th)[i] = make_uint2(packbf(s.x * rs, s.y * rs), packbf(s.z * rs, s.w * rs));
}

// ---------------- final head ----------------
__global__ void head_kernel(const float* __restrict__ h2, const float* __restrict__ W3,
                            const float* __restrict__ b3, float* __restrict__ out)
{
    const int row = blockIdx.x;
    const int t = threadIdx.x;
    const float* hr = h2 + (size_t)row * H2DIM;

    float a0 = 0.f, a1 = 0.f, a2 = 0.f, a3 = 0.f;
    for (int k = t; k < H2DIM; k += 64) {
        const float hv = hr[k];
        a0 = fmaf(hv, W3[k * 4 + 0], a0);
        a1 = fmaf(hv, W3[k * 4 + 1], a1);
        a2 = fmaf(hv, W3[k * 4 + 2], a2);
        a3 = fmaf(hv, W3[k * 4 + 3], a3);
    }
    __shared__ float s0[64], s1[64], s2[64], s3[64];
    s0[t] = a0; s1[t] = a1; s2[t] = a2; s3[t] = a3;
    __syncthreads();
    for (int off = 32; off > 0; off >>= 1) {
        if (t < off) {
            s0[t] += s0[t + off]; s1[t] += s1[t + off];
            s2[t] += s2[t + off]; s3[t] += s3[t + off];
        }
        __syncthreads();
    }
    if (t == 0) {
        const float r0 = s0[0] + b3[0];
        const float r1 = s1[0] + b3[1];
        const float r2 = s2[0] + b3[2];
        const float r3 = s3[0] + b3[3];
        out[0 * NROWS + row] = r0;
        out[1 * NROWS + row] = softplus_stable(r1) + 1e-6f;
        out[2 * NROWS + row] = fminf(softplus_stable(r2), 28.0f) + 1.01f;
        out[3 * NROWS + row] = softplus_stable(r3) + 1e-6f;
    }
}

// ---------------- host side ----------------
template<typename T>
static T* sym(const void* s) {
    void* p = nullptr;
    cudaGetSymbolAddress(&p, (const void*)s);
    return (T*)p;
}

template<int PASSES, int EPI, bool OSPLIT, typename OT>
static void launch_gemm(const bf16* Ah, const bf16* Al, const bf16* Bh, const bf16* Bl,
                        const float* bias, const float* res, OT* C, bf16* Cl, float* psum,
                        int N, int Ktot, int splits, float scale)
{
    int smemB = NST * ((PASSES == 1) ? 32768 : 65536);
    cudaFuncSetAttribute(bgemm<PASSES, EPI, OSPLIT, OT>,
                         cudaFuncAttributeMaxDynamicSharedMemorySize, smemB);
    dim3 grid(N / 128, NROWS / 128, splits);
    bgemm<PASSES, EPI, OSPLIT, OT><<<grid, 128, smemB>>>(
        Ah, Al, Bh, Bl, bias, res, C, Cl, psum, N, Ktot, Ktot / splits, scale);
}

extern "C" void kernel_launch(void* const* d_in, const int* in_sizes, int n_in,
                              void* d_out, int out_size)
{
    const float* X      = (const float*)d_in[0];
    const float* ctx_k  = (const float*)d_in[1];
    const float* ctx_v  = (const float*)d_in[2];
    const float* Wq_hop = (const float*)d_in[3];
    const float* alpha  = (const float*)d_in[4];
    const float* Wq_mol = (const float*)d_in[5];
    const float* Wk_mol = (const float*)d_in[6];
    const float* Wg     = (const float*)d_in[7];
    const float* bg     = (const float*)d_in[8];
    const float* W1     = (const float*)d_in[9];
    const float* b1     = (const float*)d_in[10];
    const float* W2     = (const float*)d_in[11];
    const float* b2     = (const float*)d_in[12];
    const float* W3     = (const float*)d_in[13];
    const float* b3     = (const float*)d_in[14];
    float* out = (float*)d_out;

    bf16 *S = sym<bf16>(g_S), *Vt = sym<bf16>(g_Vt), *Kc = sym<bf16>(g_Kc);
    bf16 *Xh = sym<bf16>(g_Xh), *Xl = sym<bf16>(g_Xl), *Qb = sym<bf16>(g_Qb);
    bf16 *X2h = sym<bf16>(g_X2h), *X2th = sym<bf16>(g_X2th);
    bf16 *Qmh = sym<bf16>(g_Qmh), *Kmh = sym<bf16>(g_Kmh);
    bf16 *A2h = sym<bf16>(g_A2h), *Th = sym<bf16>(g_Th);
    bf16 *Hh = sym<bf16>(g_Hh), *Hl = sym<bf16>(g_Hl);
    bf16 *H1h = sym<bf16>(g_H1h), *H1l = sym<bf16>(g_H1l);
    bf16 *Wqh_h = sym<bf16>(g_Wqh_h), *Wqh_l = sym<bf16>(g_Wqh_l);
    bf16 *Wqm_h = sym<bf16>(g_Wqm_h), *Wkm_h = sym<bf16>(g_Wkm_h);
    bf16 *Wg_h = sym<bf16>(g_Wg_h);
    bf16 *W1_h = sym<bf16>(g_W1_h), *W1_l = sym<bf16>(g_W1_l);
    bf16 *W2_h = sym<bf16>(g_W2_h), *W2_l = sym<bf16>(g_W2_l);
    float *X2 = sym<float>(g_X2), *H2 = sym<float>(g_H2);
    float *invS = sym<float>(g_invS), *invA = sym<float>(g_invA);
    float *part = sym<float>(g_part), *psum = sym<float>(g_psum);

    const float inv_sqrt_dinner = 0.0625f;              // 1/sqrt(256)
    const float inv_sqrt_d = 0.036084391824351615f;     // 1/sqrt(768)
    const dim3 tb(32, 8);

    // ---- preprocessing: K-major bf16 operands ----
    conv_hl_kernel<<<(NROWS * DDIM / 4 + 255) / 256, 256>>>(X, Xh, Xl, (size_t)NROWS * DDIM / 4);
    conv_hl_kernel<<<((size_t)MCTX * DINNER / 4 + 255) / 256, 256>>>(ctx_k, Kc, nullptr, (size_t)MCTX * DINNER / 4);
    transpose_hl_kernel<<<dim3(MCTX / 32, DDIM / 32), tb>>>(ctx_v, Vt, nullptr, MCTX, DDIM);
    transpose_hl_kernel<<<dim3(DDIM / 32, DINNER / 32), tb>>>(Wq_hop, Wqh_h, Wqh_l, DDIM, DINNER);
    transpose_hl_kernel<<<dim3(DDIM / 32, DDIM / 32), tb>>>(Wq_mol, Wqm_h, nullptr, DDIM, DDIM);
    transpose_hl_kernel<<<dim3(DDIM / 32, DDIM / 32), tb>>>(Wk_mol, Wkm_h, nullptr, DDIM, DDIM);
    transpose_hl_kernel<<<dim3(DDIM / 32, DDIM / 32), tb>>>(Wg, Wg_h, nullptr, DDIM, DDIM);
    transpose_hl_kernel<<<dim3(DDIM / 32, H1DIM / 32), tb>>>(W1, W1_h, W1_l, DDIM, H1DIM);
    transpose_hl_kernel<<<dim3(H1DIM / 32, H2DIM / 32), tb>>>(W2, W2_h, W2_l, H1DIM, H2DIM);

    // 1. Q = X @ Wq_hop -> bf16                 (N=256, K=768)   split-3
    launch_gemm<3, EPI_NONE, false>(Xh, Xl, Wqh_h, Wqh_l, nullptr, nullptr,
                                    Qb, nullptr, nullptr, DINNER, DDIM, 1, 1.0f);

    // 2. S = exp(Q @ ctx_k^T / 16) -> bf16 + fused row partials   (N=32768, K=256)
    launch_gemm<1, EPI_EXP, false>(Qb, nullptr, Kc, nullptr, nullptr, nullptr,
                                   S, nullptr, psum, MCTX, DINNER, 1, inv_sqrt_dinner);

    // 3. invS = 1 / sum of 256 tile partials
    rowsum_combine_kernel<<<NROWS / 256, 256>>>(psum, invS, MCTX / 128);

    // 4. enriched partials = S @ Vt^T (split-K=8); X2 = blend*(invS*sum) + (1-blend)*X
    launch_gemm<1, EPI_NONE, false>(S, nullptr, Vt, nullptr, nullptr, nullptr,
                                    part, nullptr, nullptr, DDIM, MCTX, 8, 1.0f);
    reduce_blend_kernel<<<NROWS * DDIM / 1024, 256>>>(part, X, invS, alpha, X2, X2h, 8);
    transpose_hl_kernel<<<dim3(NROWS / 32, DDIM / 32), tb>>>(X2, X2th, nullptr, NROWS, DDIM);

    // 5. Qm, Km  (N=768, K=768)  single (damped)
    launch_gemm<1, EPI_NONE, false>(X2h, nullptr, Wqm_h, nullptr, nullptr, nullptr,
                                    Qmh, nullptr, nullptr, DDIM, DDIM, 1, 1.0f);
    launch_gemm<1, EPI_NONE, false>(X2h, nullptr, Wkm_h, nullptr, nullptr, nullptr,
                                    Kmh, nullptr, nullptr, DDIM, DDIM, 1, 1.0f);

    // 6. A2 = exp(Qm @ Km^T / sqrt(768)) -> bf16 + fused row partials  (N=4096, K=768)
    launch_gemm<1, EPI_EXP, false>(Qmh, nullptr, Kmh, nullptr, nullptr, nullptr,
                                   A2h, nullptr, psum, NROWS, DDIM, 1, inv_sqrt_d);

    // 7. invA = 1 / sum of 32 tile partials
    rowsum_combine_kernel<<<NROWS / 256, 256>>>(psum, invA, NROWS / 128);

    // 8. T partials = A2 @ X2 (split-K=4); T = invA*sum -> bf16   single
    launch_gemm<1, EPI_NONE, false>(A2h, nullptr, X2th, nullptr, nullptr, nullptr,
                                    part, nullptr, nullptr, DDIM, NROWS, 4, 1.0f);
    reduce_rs_kernel<<<NROWS * DDIM / 1024, 256>>>(part, invA, Th, 4);

    // 9. H = X2 + gelu(T @ Wg + bg)  (N=768, K=768)  single; split hi/lo output
    launch_gemm<1, EPI_BGR, true>(Th, nullptr, Wg_h, nullptr, bg, X2,
                                  Hh, Hl, nullptr, DDIM, DDIM, 1, 1.0f);

    // 10. H1 = gelu(H @ W1 + b1)  (N=512, K=768)  split-3
    launch_gemm<3, EPI_BG, true>(Hh, Hl, W1_h, W1_l, b1, nullptr,
                                 H1h, H1l, nullptr, H1DIM, DDIM, 1, 1.0f);

    // 11. H2 = gelu(H1 @ W2 + b2) -> fp32  (N=256, K=512)  split-3
    launch_gemm<3, EPI_BG, false>(H1h, H1l, W2_h, W2_l, b2, nullptr,
                                  H2, nullptr, nullptr, H2DIM, H1DIM, 1, 1.0f);

    // 12. head -> out (mu | v | a | b)
    head_kernel<<<NROWS, 64>>>(H2, W3, b3, out);

    (void)in_sizes; (void)n_in; (void)out_size;
}